// round 9
// baseline (speedup 1.0000x reference)
#include <cuda_runtime.h>
#include <cuda_bf16.h>
#include <math.h>
#include <stdint.h>

#define B_      1024
#define P_      11
#define C_      8
#define H_      512
#define T_      200
#define L_      2000
#define STRIDE_ 180
#define M_      (B_*P_*C_)

typedef unsigned long long u64;
typedef unsigned int u32;
typedef __nv_bfloat16 bf16;

// ---------------- scratch (device globals) ----------------
__device__ bf16 g_Hh[(size_t)M_ * 512];
__device__ bf16 g_Hl[(size_t)M_ * 512];
__device__ bf16 g_W1th[512 * 512];
__device__ bf16 g_W1tl[512 * 512];
__device__ bf16 g_W2th[256 * 512];
__device__ bf16 g_W2tl[256 * 512];
__device__ float g_patches[(size_t)M_ * T_];
__device__ bf16 g_rech[(size_t)B_ * L_ * 8];
__device__ bf16 g_recl[(size_t)B_ * L_ * 8];
__device__ bf16 g_r1h[(size_t)B_ * L_ * 32];
__device__ bf16 g_r1l[(size_t)B_ * L_ * 32];
__device__ bf16 g_r2h[(size_t)B_ * L_ * 16];
__device__ bf16 g_r2l[(size_t)B_ * L_ * 16];
__device__ bf16 g_cw1h[32 * 128];
__device__ bf16 g_cw1l[32 * 128];
__device__ bf16 g_w2h[16 * 480];
__device__ bf16 g_w2l[16 * 480];
__device__ bf16 g_cw3h[8 * 240];
__device__ bf16 g_cw3l[8 * 240];

__device__ __forceinline__ float gelu_erf(float x) {
    return 0.5f * x * (1.0f + erff(x * 0.7071067811865476f));
}

// ---------------- warp MMA primitives ----------------
__device__ __forceinline__ uint32_t smem_u32(const void* p) {
    uint32_t a;
    asm("{ .reg .u64 t; cvta.to.shared.u64 t, %1; cvt.u32.u64 %0, t; }" : "=r"(a) : "l"(p));
    return a;
}
__device__ __forceinline__ void ldsm_x4(u32& r0, u32& r1, u32& r2, u32& r3, u32 addr) {
    asm volatile("ldmatrix.sync.aligned.m8n8.x4.shared.b16 {%0,%1,%2,%3}, [%4];"
        : "=r"(r0), "=r"(r1), "=r"(r2), "=r"(r3) : "r"(addr));
}
__device__ __forceinline__ void ldsm_x2(u32& r0, u32& r1, u32 addr) {
    asm volatile("ldmatrix.sync.aligned.m8n8.x2.shared.b16 {%0,%1}, [%2];"
        : "=r"(r0), "=r"(r1) : "r"(addr));
}
__device__ __forceinline__ void mma_bf16(float* d, const u32* a, const u32* b) {
    asm volatile("mma.sync.aligned.m16n8k16.row.col.f32.bf16.bf16.f32 "
        "{%0,%1,%2,%3}, {%4,%5,%6,%7}, {%8,%9}, {%0,%1,%2,%3};"
        : "+f"(d[0]), "+f"(d[1]), "+f"(d[2]), "+f"(d[3])
        : "r"(a[0]), "r"(a[1]), "r"(a[2]), "r"(a[3]), "r"(b[0]), "r"(b[1]));
}
__device__ __forceinline__ void split_bf16(float v, bf16& h, bf16& l) {
    h = __float2bfloat16(v);
    l = __float2bfloat16(v - __bfloat162float(h));
}

// ================= prep kernels (weights only) =================
__global__ void transp_split_kernel(const float* __restrict__ W,
                                    bf16* __restrict__ th, bf16* __restrict__ tl,
                                    int Kdim, int Nsrc, int Npad)
{
    int idx = blockIdx.x * 256 + threadIdx.x;
    if (idx >= Npad * Kdim) return;
    int n = idx / Kdim, k = idx - n * Kdim;
    float f = (n < Nsrc) ? W[(size_t)k * Nsrc + n] : 0.0f;
    split_bf16(f, th[idx], tl[idx]);
}

__global__ void w1c_prep_kernel(const float* __restrict__ w,
                                bf16* __restrict__ wh, bf16* __restrict__ wl)
{
    int idx = blockIdx.x * 256 + threadIdx.x;
    if (idx >= 32 * 128) return;
    int co = idx >> 7, c = idx & 127;
    int ks = c >> 4, rem = c & 15;
    int tap = 2 * ks + (rem >> 3);
    int ic = rem & 7;
    float f = (tap < 15) ? w[((size_t)co * 8 + ic) * 15 + tap] : 0.0f;
    split_bf16(f, wh[idx], wl[idx]);
}

__global__ void w2_prep_kernel(const float* __restrict__ w,
                               bf16* __restrict__ wh, bf16* __restrict__ wl)
{
    int idx = blockIdx.x * 256 + threadIdx.x;
    if (idx >= 16 * 480) return;
    int co = idx / 480, c = idx - co * 480;
    int k = c >> 5, ic = c & 31;
    float f = w[((size_t)co * 32 + ic) * 15 + k];
    split_bf16(f, wh[idx], wl[idx]);
}

__global__ void w3c_prep_kernel(const float* __restrict__ w,
                                bf16* __restrict__ wh, bf16* __restrict__ wl)
{
    int idx = blockIdx.x * 256 + threadIdx.x;
    if (idx >= 8 * 240) return;
    int co = idx / 240, c = idx - co * 240;
    int k = c >> 4, ic = c & 15;
    float f = w[((size_t)co * 16 + ic) * 15 + k];
    split_bf16(f, wh[idx], wl[idx]);
}

// ================= HMMA GEMM =================
#define ASTR 40

template<bool A_FP32, bool GELU_SPLIT>
__global__ void __launch_bounds__(256, 2) gemm_hmma(
    const float* __restrict__ Af,
    const bf16* __restrict__ Ah, const bf16* __restrict__ Al,
    const bf16* __restrict__ Bh, const bf16* __restrict__ Bl,
    const float* __restrict__ bias, int Nvalid,
    bf16* __restrict__ outHh, bf16* __restrict__ outHl, float* __restrict__ outF)
{
    __shared__ __align__(16) bf16 sAh[128 * ASTR];
    __shared__ __align__(16) bf16 sAl[128 * ASTR];
    __shared__ __align__(16) bf16 sBh[64 * ASTR];
    __shared__ __align__(16) bf16 sBl[64 * ASTR];

    const int tid  = threadIdx.x;
    const int lane = tid & 31;
    const int wid  = tid >> 5;
    const int wm   = wid & 3;
    const int wn   = wid >> 2;
    const int bm   = blockIdx.y * 128;
    const int bn   = blockIdx.x * 64;

    float acc[2][4][4];
#pragma unroll
    for (int i = 0; i < 2; i++)
#pragma unroll
        for (int j = 0; j < 4; j++)
#pragma unroll
            for (int q = 0; q < 4; q++) acc[i][j][q] = 0.0f;

    const int ar = tid >> 2;
    const int aq = (tid & 3) * 8;
    const size_t gA0 = (size_t)(bm + ar) * 512 + aq;
    const size_t gA1 = (size_t)(bm + ar + 64) * 512 + aq;
    const size_t gB0 = (size_t)(bn + ar) * 512 + aq;

    const u32 sbAh = smem_u32(sAh), sbAl = smem_u32(sAl);
    const u32 sbBh = smem_u32(sBh), sbBl = smem_u32(sBl);

    const int lrow = lane & 15;
    const int lhalf = (lane >> 4) * 8;
    const u32 aoffA0 = ((wm * 32 +      lrow) * ASTR + lhalf) * 2;
    const u32 aoffA1 = ((wm * 32 + 16 + lrow) * ASTR + lhalf) * 2;
    const u32 aoffB0 = ((wn * 32 +      lrow) * ASTR + lhalf) * 2;
    const u32 aoffB1 = ((wn * 32 + 16 + lrow) * ASTR + lhalf) * 2;

    uint4 pah0, pah1, pal0, pal1;
    float4 fa0, fa1, fb0, fb1;
    uint4 pbh, pbl;

    if (A_FP32) {
        fa0 = *(const float4*)(Af + gA0); fa1 = *(const float4*)(Af + gA0 + 4);
        fb0 = *(const float4*)(Af + gA1); fb1 = *(const float4*)(Af + gA1 + 4);
    } else {
        pah0 = *(const uint4*)(Ah + gA0); pah1 = *(const uint4*)(Ah + gA1);
        pal0 = *(const uint4*)(Al + gA0); pal1 = *(const uint4*)(Al + gA1);
    }
    pbh = *(const uint4*)(Bh + gB0); pbl = *(const uint4*)(Bl + gB0);

    const int sA0 = ar * ASTR + aq, sA1 = (ar + 64) * ASTR + aq, sB0 = ar * ASTR + aq;

    for (int kt = 0; kt < 16; kt++) {
        if (A_FP32) {
            float f0[8] = {fa0.x, fa0.y, fa0.z, fa0.w, fa1.x, fa1.y, fa1.z, fa1.w};
            float f1[8] = {fb0.x, fb0.y, fb0.z, fb0.w, fb1.x, fb1.y, fb1.z, fb1.w};
            unsigned short h0[8], l0[8], h1[8], l1[8];
#pragma unroll
            for (int j = 0; j < 8; j++) {
                bf16 h, l;
                split_bf16(f0[j], h, l);
                h0[j] = __bfloat16_as_ushort(h); l0[j] = __bfloat16_as_ushort(l);
                split_bf16(f1[j], h, l);
                h1[j] = __bfloat16_as_ushort(h); l1[j] = __bfloat16_as_ushort(l);
            }
            *(uint4*)(sAh + sA0) = *(uint4*)h0; *(uint4*)(sAl + sA0) = *(uint4*)l0;
            *(uint4*)(sAh + sA1) = *(uint4*)h1; *(uint4*)(sAl + sA1) = *(uint4*)l1;
        } else {
            *(uint4*)(sAh + sA0) = pah0; *(uint4*)(sAh + sA1) = pah1;
            *(uint4*)(sAl + sA0) = pal0; *(uint4*)(sAl + sA1) = pal1;
        }
        *(uint4*)(sBh + sB0) = pbh; *(uint4*)(sBl + sB0) = pbl;
        __syncthreads();

        if (kt < 15) {
            int k0 = (kt + 1) * 32;
            if (A_FP32) {
                fa0 = *(const float4*)(Af + gA0 + k0); fa1 = *(const float4*)(Af + gA0 + k0 + 4);
                fb0 = *(const float4*)(Af + gA1 + k0); fb1 = *(const float4*)(Af + gA1 + k0 + 4);
            } else {
                pah0 = *(const uint4*)(Ah + gA0 + k0); pah1 = *(const uint4*)(Ah + gA1 + k0);
                pal0 = *(const uint4*)(Al + gA0 + k0); pal1 = *(const uint4*)(Al + gA1 + k0);
            }
            pbh = *(const uint4*)(Bh + gB0 + k0); pbl = *(const uint4*)(Bl + gB0 + k0);
        }

#pragma unroll
        for (int kk = 0; kk < 2; kk++) {
            const u32 kadd = kk * 32;
            u32 a_h[2][4], a_l[2][4];
            ldsm_x4(a_h[0][0], a_h[0][1], a_h[0][2], a_h[0][3], sbAh + aoffA0 + kadd);
            ldsm_x4(a_h[1][0], a_h[1][1], a_h[1][2], a_h[1][3], sbAh + aoffA1 + kadd);
            ldsm_x4(a_l[0][0], a_l[0][1], a_l[0][2], a_l[0][3], sbAl + aoffA0 + kadd);
            ldsm_x4(a_l[1][0], a_l[1][1], a_l[1][2], a_l[1][3], sbAl + aoffA1 + kadd);

            u32 t0, t1, t2, t3;
            u32 b_h[4][2], b_l[4][2];
            ldsm_x4(t0, t1, t2, t3, sbBh + aoffB0 + kadd);
            b_h[0][0] = t0; b_h[0][1] = t2; b_h[1][0] = t1; b_h[1][1] = t3;
            ldsm_x4(t0, t1, t2, t3, sbBh + aoffB1 + kadd);
            b_h[2][0] = t0; b_h[2][1] = t2; b_h[3][0] = t1; b_h[3][1] = t3;
            ldsm_x4(t0, t1, t2, t3, sbBl + aoffB0 + kadd);
            b_l[0][0] = t0; b_l[0][1] = t2; b_l[1][0] = t1; b_l[1][1] = t3;
            ldsm_x4(t0, t1, t2, t3, sbBl + aoffB1 + kadd);
            b_l[2][0] = t0; b_l[2][1] = t2; b_l[3][0] = t1; b_l[3][1] = t3;

            // term-outer order: consecutive MMAs hit different accumulators
#pragma unroll
            for (int s = 0; s < 3; s++) {
#pragma unroll
                for (int mi = 0; mi < 2; mi++)
#pragma unroll
                    for (int ni = 0; ni < 4; ni++) {
                        const u32* aa = (s == 2) ? a_l[mi] : a_h[mi];
                        const u32* bb = (s == 1) ? b_l[ni] : b_h[ni];
                        mma_bf16(acc[mi][ni], aa, bb);
                    }
            }
        }
        __syncthreads();
    }

    const int grp = lane >> 2;
    const int qc  = (lane & 3) * 2;
#pragma unroll
    for (int mi = 0; mi < 2; mi++) {
        const int r0 = bm + wm * 32 + mi * 16 + grp;
        const int r1 = r0 + 8;
#pragma unroll
        for (int ni = 0; ni < 4; ni++) {
            const int col = bn + wn * 32 + ni * 8 + qc;
            float bv0 = __ldg(&bias[col]), bv1 = __ldg(&bias[col + 1]);
            float v00 = acc[mi][ni][0] + bv0, v01 = acc[mi][ni][1] + bv1;
            float v10 = acc[mi][ni][2] + bv0, v11 = acc[mi][ni][3] + bv1;
            if (GELU_SPLIT) {
                v00 = gelu_erf(v00); v01 = gelu_erf(v01);
                v10 = gelu_erf(v10); v11 = gelu_erf(v11);
                bf16 h0, h1, l0, l1;
                split_bf16(v00, h0, l0); split_bf16(v01, h1, l1);
                size_t i0 = (size_t)r0 * 256 + (col >> 1);
                reinterpret_cast<__nv_bfloat162*>(outHh)[i0] = __halves2bfloat162(h0, h1);
                reinterpret_cast<__nv_bfloat162*>(outHl)[i0] = __halves2bfloat162(l0, l1);
                split_bf16(v10, h0, l0); split_bf16(v11, h1, l1);
                size_t i1 = (size_t)r1 * 256 + (col >> 1);
                reinterpret_cast<__nv_bfloat162*>(outHh)[i1] = __halves2bfloat162(h0, h1);
                reinterpret_cast<__nv_bfloat162*>(outHl)[i1] = __halves2bfloat162(l0, l1);
            } else {
                if (col < Nvalid) {
                    *(float2*)(outF + (size_t)r0 * Nvalid + col) = make_float2(v00, v01);
                    *(float2*)(outF + (size_t)r1 * Nvalid + col) = make_float2(v10, v11);
                }
            }
        }
    }
}

// ================= overlap-add -> rec bf16 split [b][l][8] =================
__global__ void overlap_add_v3(const float* __restrict__ patches,
                               bf16* __restrict__ rech, bf16* __restrict__ recl)
{
    const int b  = blockIdx.y;
    const int l  = blockIdx.x * 256 + threadIdx.x;
    if (l >= L_) return;

    int i_lo = l - (T_ - 1);
    i_lo = (i_lo > 0) ? (i_lo + STRIDE_ - 1) / STRIDE_ : 0;
    int i_hi = l / STRIDE_;
    if (i_hi > P_ - 1) i_hi = P_ - 1;

    int np = 0, pi[2], pt[2];
    float wv[2], ws = 0.0f;
    for (int i = i_lo; i <= i_hi; i++) {
        int t = l - i * STRIDE_;
        float w;
        if (t < 50)        w = (float)t * (1.0f / 49.0f);
        else if (t >= 150) w = (float)(199 - t) * (1.0f / 49.0f);
        else               w = 1.0f;
        pi[np] = i; pt[np] = t; wv[np] = w; ws += w; np++;
    }
    float ews = fmaxf(ws, 1e-8f);

    unsigned short hh[8], ll[8];
#pragma unroll
    for (int c = 0; c < 8; c++) {
        float v = 0.0f;
        for (int j = 0; j < np; j++)
            v += patches[(((size_t)b * P_ + pi[j]) * C_ + c) * T_ + pt[j]] * wv[j];
        v = v / ews;
        bf16 h, lo; split_bf16(v, h, lo);
        hh[c] = __bfloat16_as_ushort(h);
        ll[c] = __bfloat16_as_ushort(lo);
    }
    size_t o = ((size_t)b * L_ + l) * 8;
    *(uint4*)(rech + o) = *(uint4*)hh;
    *(uint4*)(recl + o) = *(uint4*)ll;
}

// ================= conv1: 8->32 k15, HMMA, 3-bank accumulators =================
#define C1XSTR 40
#define C1WSTR 136
__global__ void __launch_bounds__(256) conv1_hmma(
    const bf16* __restrict__ rech, const bf16* __restrict__ recl,
    const bf16* __restrict__ wh, const bf16* __restrict__ wl,
    const float* __restrict__ bias,
    bf16* __restrict__ r1h, bf16* __restrict__ r1l)
{
    __shared__ __align__(16) bf16 sXh[143 * C1XSTR];
    __shared__ __align__(16) bf16 sXl[143 * C1XSTR];
    __shared__ __align__(16) bf16 sWh[32 * C1WSTR];
    __shared__ __align__(16) bf16 sWl[32 * C1WSTR];

    const int tid  = threadIdx.x;
    const int lane = tid & 31;
    const int wm   = tid >> 5;
    const int b    = blockIdx.y;

    for (int i = tid; i < 32 * 64; i += 256) {
        int r = i >> 6, q = i & 63;
        ((u32*)sWh)[r * (C1WSTR/2) + q] = ((const u32*)wh)[r * 64 + q];
        ((u32*)sWl)[r * (C1WSTR/2) + q] = ((const u32*)wl)[r * 64 + q];
    }

    const u32 sbXh = smem_u32(sXh), sbXl = smem_u32(sXl);
    const u32 sbWh = smem_u32(sWh), sbWl = smem_u32(sWl);
    const int lrow = lane & 15;
    const int lhalf = (lane >> 4) * 8;
    const int grp = lane >> 2, qc = (lane & 3) * 2;

    for (int tile = 0; tile < 2; tile++) {
        const int t0 = blockIdx.x * 256 + tile * 128;
        __syncthreads();
        for (int i = tid; i < 143 * 2; i += 256) {
            int r = i >> 1, half = i & 1;
            int gp = t0 + r - 7 + half;
            uint4 vh = make_uint4(0,0,0,0), vl = vh;
            if (gp >= 0 && gp < L_) {
                size_t o = ((size_t)b * L_ + gp) * 8;
                vh = *(const uint4*)(rech + o);
                vl = *(const uint4*)(recl + o);
            }
            *(uint4*)(sXh + r * C1XSTR + half * 8) = vh;
            *(uint4*)(sXl + r * C1XSTR + half * 8) = vl;
        }
        __syncthreads();

        float a0[4][4], a1[4][4], a2[4][4];   // 3 banks
#pragma unroll
        for (int ni = 0; ni < 4; ni++)
#pragma unroll
            for (int q = 0; q < 4; q++) { a0[ni][q] = 0.f; a1[ni][q] = 0.f; a2[ni][q] = 0.f; }

#pragma unroll
        for (int k = 0; k < 8; k++) {
            u32 aadd = (u32)((wm * 16 + lrow + 2 * k) * C1XSTR + lhalf) * 2;
            u32 ah[4], al[4];
            ldsm_x4(ah[0], ah[1], ah[2], ah[3], sbXh + aadd);
            ldsm_x4(al[0], al[1], al[2], al[3], sbXl + aadd);

            u32 t0r, t1r, t2r, t3r;
            u32 bh[4][2], bl[4][2];
#pragma unroll
            for (int na2 = 0; na2 < 2; na2++) {
                u32 badd = (u32)((na2 * 16 + lrow) * C1WSTR + k * 16 + lhalf) * 2;
                ldsm_x4(t0r, t1r, t2r, t3r, sbWh + badd);
                bh[na2*2][0] = t0r; bh[na2*2][1] = t2r;
                bh[na2*2+1][0] = t1r; bh[na2*2+1][1] = t3r;
                ldsm_x4(t0r, t1r, t2r, t3r, sbWl + badd);
                bl[na2*2][0] = t0r; bl[na2*2][1] = t2r;
                bl[na2*2+1][0] = t1r; bl[na2*2+1][1] = t3r;
            }
#pragma unroll
            for (int ni = 0; ni < 4; ni++) mma_bf16(a0[ni], ah, bh[ni]);
#pragma unroll
            for (int ni = 0; ni < 4; ni++) mma_bf16(a1[ni], ah, bl[ni]);
#pragma unroll
            for (int ni = 0; ni < 4; ni++) mma_bf16(a2[ni], al, bh[ni]);
        }
        __syncthreads();

        u32* stgh = (u32*)sXh;
        u32* stgl = (u32*)sXl;
#pragma unroll
        for (int ni = 0; ni < 4; ni++) {
            float acc[4];
#pragma unroll
            for (int q = 0; q < 4; q++) acc[q] = a0[ni][q] + a1[ni][q] + a2[ni][q];
            int ch = ni * 8 + qc;
            float bv0 = __ldg(&bias[ch]), bv1 = __ldg(&bias[ch + 1]);
            int p0 = wm * 16 + grp, p1 = p0 + 8;
            float v00 = gelu_erf(acc[0] + bv0), v01 = gelu_erf(acc[1] + bv1);
            float v10 = gelu_erf(acc[2] + bv0), v11 = gelu_erf(acc[3] + bv1);
            bf16 h0, h1, l0, l1;
            split_bf16(v00, h0, l0); split_bf16(v01, h1, l1);
            __nv_bfloat162 th = __halves2bfloat162(h0, h1), tl = __halves2bfloat162(l0, l1);
            stgh[p0 * 17 + ni * 4 + (lane & 3)] = *(u32*)&th;
            stgl[p0 * 17 + ni * 4 + (lane & 3)] = *(u32*)&tl;
            split_bf16(v10, h0, l0); split_bf16(v11, h1, l1);
            th = __halves2bfloat162(h0, h1); tl = __halves2bfloat162(l0, l1);
            stgh[p1 * 17 + ni * 4 + (lane & 3)] = *(u32*)&th;
            stgl[p1 * 17 + ni * 4 + (lane & 3)] = *(u32*)&tl;
        }
        __syncthreads();
        for (int i = tid; i < 128 * 16; i += 256) {
            int p = i >> 4, q = i & 15;
            int l = t0 + p;
            if (l < L_) {
                size_t o = ((size_t)b * L_ + l) * 16 + q;
                ((u32*)r1h)[o] = stgh[p * 17 + q];
                ((u32*)r1l)[o] = stgl[p * 17 + q];
            }
        }
    }
}

// ================= conv2: 32->16 k15, HMMA, 3-bank accumulators =================
#define X2STR 40
#define W2STR 488
__global__ void __launch_bounds__(256) conv2_hmma(
    const bf16* __restrict__ r1h, const bf16* __restrict__ r1l,
    const bf16* __restrict__ wh, const bf16* __restrict__ wl,
    const float* __restrict__ bias,
    bf16* __restrict__ r2h, bf16* __restrict__ r2l)
{
    __shared__ __align__(16) bf16 sXh[144 * X2STR];
    __shared__ __align__(16) bf16 sXl[144 * X2STR];
    __shared__ __align__(16) bf16 sWh[16 * W2STR];
    __shared__ __align__(16) bf16 sWl[16 * W2STR];

    const int tid  = threadIdx.x;
    const int lane = tid & 31;
    const int wm   = tid >> 5;
    const int b    = blockIdx.y;

    for (int i = tid; i < 16 * 240; i += 256) {
        int r = i / 240, c = i - r * 240;
        ((u32*)sWh)[r * (W2STR/2) + c] = ((const u32*)wh)[r * 240 + c];
        ((u32*)sWl)[r * (W2STR/2) + c] = ((const u32*)wl)[r * 240 + c];
    }

    const u32 sbXh = smem_u32(sXh), sbXl = smem_u32(sXl);
    const u32 sbWh = smem_u32(sWh), sbWl = smem_u32(sWl);
    const int lrow = lane & 15;
    const int lhalf = (lane >> 4) * 8;
    const u32 boff  = sbWh + ((lane & 15) * W2STR + lhalf) * 2;
    const u32 boffl = sbWl + ((lane & 15) * W2STR + lhalf) * 2;
    const int grp = lane >> 2, qc = (lane & 3) * 2;

    for (int tile = 0; tile < 2; tile++) {
        const int t0 = blockIdx.x * 256 + tile * 128;
        __syncthreads();
        for (int i = tid; i < 144 * 4; i += 256) {
            int r = i >> 2, q = i & 3;
            int gp = t0 + r - 8;
            uint4 vh = make_uint4(0,0,0,0), vl = vh;
            if (gp >= 0 && gp < L_) {
                size_t o = ((size_t)b * L_ + gp) * 32 + q * 8;
                vh = *(const uint4*)(r1h + o);
                vl = *(const uint4*)(r1l + o);
            }
            *(uint4*)(sXh + r * X2STR + q * 8) = vh;
            *(uint4*)(sXl + r * X2STR + q * 8) = vl;
        }
        __syncthreads();

        float a0[2][4], a1[2][4], a2[2][4];   // 3 banks x 2 n-atoms
#pragma unroll
        for (int ni = 0; ni < 2; ni++)
#pragma unroll
            for (int q = 0; q < 4; q++) { a0[ni][q] = 0.f; a1[ni][q] = 0.f; a2[ni][q] = 0.f; }

#pragma unroll 2
        for (int ks = 0; ks < 30; ks++) {
            const int k   = ks >> 1;
            const int icb = (ks & 1) * 16;
            const u32 aadd = (u32)((wm * 16 + lrow + k + 1) * X2STR + icb + lhalf) * 2;

            u32 ah[4], al[4];
            ldsm_x4(ah[0], ah[1], ah[2], ah[3], sbXh + aadd);
            ldsm_x4(al[0], al[1], al[2], al[3], sbXl + aadd);

            u32 t0r, t1r, t2r, t3r;
            u32 bh[2][2], bl[2][2];
            ldsm_x4(t0r, t1r, t2r, t3r, boff + ks * 32);
            bh[0][0] = t0r; bh[0][1] = t2r; bh[1][0] = t1r; bh[1][1] = t3r;
            ldsm_x4(t0r, t1r, t2r, t3r, boffl + ks * 32);
            bl[0][0] = t0r; bl[0][1] = t2r; bl[1][0] = t1r; bl[1][1] = t3r;

#pragma unroll
            for (int ni = 0; ni < 2; ni++) mma_bf16(a0[ni], ah, bh[ni]);
#pragma unroll
            for (int ni = 0; ni < 2; ni++) mma_bf16(a1[ni], ah, bl[ni]);
#pragma unroll
            for (int ni = 0; ni < 2; ni++) mma_bf16(a2[ni], al, bh[ni]);
        }
        __syncthreads();

        u32* stgh = (u32*)sXh;
        u32* stgl = (u32*)sXl;
#pragma unroll
        for (int ni = 0; ni < 2; ni++) {
            float acc[4];
#pragma unroll
            for (int q = 0; q < 4; q++) acc[q] = a0[ni][q] + a1[ni][q] + a2[ni][q];
            int ch = ni * 8 + qc;
            float bv0 = __ldg(&bias[ch]), bv1 = __ldg(&bias[ch + 1]);
            int p0 = wm * 16 + grp, p1 = p0 + 8;
            float v00 = gelu_erf(acc[0] + bv0), v01 = gelu_erf(acc[1] + bv1);
            float v10 = gelu_erf(acc[2] + bv0), v11 = gelu_erf(acc[3] + bv1);
            bf16 h0, h1, l0, l1;
            split_bf16(v00, h0, l0); split_bf16(v01, h1, l1);
            __nv_bfloat162 th = __halves2bfloat162(h0, h1), tl = __halves2bfloat162(l0, l1);
            stgh[p0 * 9 + ni * 4 + (lane & 3)] = *(u32*)&th;
            stgl[p0 * 9 + ni * 4 + (lane & 3)] = *(u32*)&tl;
            split_bf16(v10, h0, l0); split_bf16(v11, h1, l1);
            th = __halves2bfloat162(h0, h1); tl = __halves2bfloat162(l0, l1);
            stgh[p1 * 9 + ni * 4 + (lane & 3)] = *(u32*)&th;
            stgl[p1 * 9 + ni * 4 + (lane & 3)] = *(u32*)&tl;
        }
        __syncthreads();
        for (int i = tid; i < 128 * 8; i += 256) {
            int p = i >> 3, q = i & 7;
            int l = t0 + p;
            if (l < L_) {
                size_t o = ((size_t)b * L_ + l) * 8 + q;
                ((u32*)r2h)[o] = stgh[p * 9 + q];
                ((u32*)r2l)[o] = stgl[p * 9 + q];
            }
        }
    }
}

// ================= conv3: 16->8 k15 HMMA + residual + pointwise, 3-bank =================
#define X3STR 40
#define W3STR 248
__global__ void __launch_bounds__(256) conv3_hmma(
    const bf16* __restrict__ r2h, const bf16* __restrict__ r2l,
    const bf16* __restrict__ wh, const bf16* __restrict__ wl,
    const float* __restrict__ bias,
    const bf16* __restrict__ rech, const bf16* __restrict__ recl,
    const float* __restrict__ pw, const float* __restrict__ pb,
    float* __restrict__ out)
{
    __shared__ __align__(16) bf16 sXh[143 * X3STR];
    __shared__ __align__(16) bf16 sXl[143 * X3STR];
    __shared__ __align__(16) bf16 sWh[8 * W3STR];
    __shared__ __align__(16) bf16 sWl[8 * W3STR];
    __shared__ float sF[128 * 9];

    const int tid  = threadIdx.x;
    const int lane = tid & 31;
    const int wm   = tid >> 5;
    const int b    = blockIdx.y;

    for (int i = tid; i < 8 * 120; i += 256) {
        int r = i / 120, c = i - r * 120;
        ((u32*)sWh)[r * (W3STR/2) + c] = ((const u32*)wh)[r * 120 + c];
        ((u32*)sWl)[r * (W3STR/2) + c] = ((const u32*)wl)[r * 120 + c];
    }

    const u32 sbXh = smem_u32(sXh), sbXl = smem_u32(sXl);
    const u32 sbWh = smem_u32(sWh), sbWl = smem_u32(sWl);
    const int lrow = lane & 15;
    const int lhalf = (lane >> 4) * 8;
    const u32 bbase = ((lane & 7) * W3STR + ((lane >> 3) & 1) * 8) * 2;
    const int grp = lane >> 2, qc = (lane & 3) * 2;

    for (int tile = 0; tile < 2; tile++) {
        const int t0 = blockIdx.x * 256 + tile * 128;
        __syncthreads();
        for (int i = tid; i < 143 * 2; i += 256) {
            int r = i >> 1, q = i & 1;
            int gp = t0 + r - 7;
            uint4 vh = make_uint4(0,0,0,0), vl = vh;
            if (gp >= 0 && gp < L_) {
                size_t o = ((size_t)b * L_ + gp) * 16 + q * 8;
                vh = *(const uint4*)(r2h + o);
                vl = *(const uint4*)(r2l + o);
            }
            *(uint4*)(sXh + r * X3STR + q * 8) = vh;
            *(uint4*)(sXl + r * X3STR + q * 8) = vl;
        }
        __syncthreads();

        float a0[4] = {0,0,0,0}, a1[4] = {0,0,0,0}, a2[4] = {0,0,0,0};
#pragma unroll
        for (int k = 0; k < 15; k++) {
            u32 aadd = (u32)((wm * 16 + lrow + k) * X3STR + lhalf) * 2;
            u32 ah[4], al[4];
            ldsm_x4(ah[0], ah[1], ah[2], ah[3], sbXh + aadd);
            ldsm_x4(al[0], al[1], al[2], al[3], sbXl + aadd);
            u32 bh[2], bl[2];
            ldsm_x2(bh[0], bh[1], sbWh + bbase + k * 32);
            ldsm_x2(bl[0], bl[1], sbWl + bbase + k * 32);
            mma_bf16(a0, ah, bh);
            mma_bf16(a1, ah, bl);
            mma_bf16(a2, al, bh);
        }
        __syncthreads();

        {
            float acc[4];
#pragma unroll
            for (int q = 0; q < 4; q++) acc[q] = a0[q] + a1[q] + a2[q];
            float bv0 = __ldg(&bias[qc]), bv1 = __ldg(&bias[qc + 1]);
            int p0 = wm * 16 + grp, p1 = p0 + 8;
            sF[p0 * 9 + qc]     = acc[0] + bv0;
            sF[p0 * 9 + qc + 1] = acc[1] + bv1;
            sF[p1 * 9 + qc]     = acc[2] + bv0;
            sF[p1 * 9 + qc + 1] = acc[3] + bv1;
        }
        __syncthreads();

        if (tid < 128) {
            int l = t0 + tid;
            if (l < L_) {
                size_t ro = ((size_t)b * L_ + l) * 8;
                uint4 vh = *(const uint4*)(rech + ro);
                uint4 vl = *(const uint4*)(recl + ro);
                const unsigned short* hs = (const unsigned short*)&vh;
                const unsigned short* ls = (const unsigned short*)&vl;
                float resid[8];
#pragma unroll
                for (int c = 0; c < 8; c++) {
                    float rv = __bfloat162float(__ushort_as_bfloat16(hs[c]))
                             + __bfloat162float(__ushort_as_bfloat16(ls[c]));
                    resid[c] = rv + sF[tid * 9 + c];
                }
#pragma unroll
                for (int o = 0; o < 8; o++) {
                    float v = __ldg(&pb[o]);
#pragma unroll
                    for (int c = 0; c < 8; c++)
                        v += __ldg(&pw[o * C_ + c]) * resid[c];
                    out[((size_t)b * C_ + o) * L_ + l] = v;
                }
            }
        }
    }
}

// ---------------- launcher ----------------
extern "C" void kernel_launch(void* const* d_in, const int* in_sizes, int n_in,
                              void* d_out, int out_size)
{
    const float* X   = (const float*)d_in[0];
    const float* W1  = (const float*)d_in[1];
    const float* b1  = (const float*)d_in[2];
    const float* W2  = (const float*)d_in[3];
    const float* b2  = (const float*)d_in[4];
    const float* rw1 = (const float*)d_in[5];
    const float* rb1 = (const float*)d_in[6];
    const float* rw2 = (const float*)d_in[7];
    const float* rb2 = (const float*)d_in[8];
    const float* rw3 = (const float*)d_in[9];
    const float* rb3 = (const float*)d_in[10];
    const float* pw  = (const float*)d_in[11];
    const float* pb  = (const float*)d_in[12];
    float* out = (float*)d_out;

    bf16 *pHh, *pHl, *pW1th, *pW1tl, *pW2th, *pW2tl;
    bf16 *pRech, *pRecl, *pR1h, *pR1l, *pR2h, *pR2l;
    bf16 *pCw1h, *pCw1l, *pW2h, *pW2l, *pCw3h, *pCw3l;
    float *pPatches;
    cudaGetSymbolAddress((void**)&pHh,   g_Hh);
    cudaGetSymbolAddress((void**)&pHl,   g_Hl);
    cudaGetSymbolAddress((void**)&pW1th, g_W1th);
    cudaGetSymbolAddress((void**)&pW1tl, g_W1tl);
    cudaGetSymbolAddress((void**)&pW2th, g_W2th);
    cudaGetSymbolAddress((void**)&pW2tl, g_W2tl);
    cudaGetSymbolAddress((void**)&pPatches, g_patches);
    cudaGetSymbolAddress((void**)&pRech, g_rech);
    cudaGetSymbolAddress((void**)&pRecl, g_recl);
    cudaGetSymbolAddress((void**)&pR1h,  g_r1h);
    cudaGetSymbolAddress((void**)&pR1l,  g_r1l);
    cudaGetSymbolAddress((void**)&pR2h,  g_r2h);
    cudaGetSymbolAddress((void**)&pR2l,  g_r2l);
    cudaGetSymbolAddress((void**)&pCw1h, g_cw1h);
    cudaGetSymbolAddress((void**)&pCw1l, g_cw1l);
    cudaGetSymbolAddress((void**)&pW2h,  g_w2h);
    cudaGetSymbolAddress((void**)&pW2l,  g_w2l);
    cudaGetSymbolAddress((void**)&pCw3h, g_cw3h);
    cudaGetSymbolAddress((void**)&pCw3l, g_cw3l);

    // launch order puts gemm1 at slot 4 (the ncu capture slot)
    transp_split_kernel<<<(512*512 + 255) / 256, 256>>>(W1, pW1th, pW1tl, 512, 512, 512);  // 1
    transp_split_kernel<<<(256*512 + 255) / 256, 256>>>(W2, pW2th, pW2tl, 512, 200, 256);  // 2
    w1c_prep_kernel<<<(32*128 + 255) / 256, 256>>>(rw1, pCw1h, pCw1l);                     // 3

    // 4: GEMM1 -- Hh/Hl = split(GELU(X @ W1 + b1))
    gemm_hmma<true, true><<<dim3(8, M_ / 128), 256>>>(
        X, nullptr, nullptr, pW1th, pW1tl, b1, 512, pHh, pHl, nullptr);

    w2_prep_kernel<<<(16*480 + 255) / 256, 256>>>(rw2, pW2h, pW2l);                        // 5
    w3c_prep_kernel<<<(8*240 + 255) / 256, 256>>>(rw3, pCw3h, pCw3l);                      // 6

    // 7: GEMM2 -- patches = H @ W2 + b2
    gemm_hmma<false, false><<<dim3(4, M_ / 128), 256>>>(
        nullptr, pHh, pHl, pW2th, pW2tl, b2, 200, nullptr, nullptr, pPatches);

    // 8: overlap-add
    overlap_add_v3<<<dim3((L_ + 255) / 256, B_), 256>>>(pPatches, pRech, pRecl);

    // 9-11: convs
    conv1_hmma<<<dim3((L_ + 255) / 256, B_), 256>>>(pRech, pRecl, pCw1h, pCw1l, rb1, pR1h, pR1l);
    conv2_hmma<<<dim3((L_ + 255) / 256, B_), 256>>>(pR1h, pR1l, pW2h, pW2l, rb2, pR2h, pR2l);
    conv3_hmma<<<dim3((L_ + 255) / 256, B_), 256>>>(pR2h, pR2l, pCw3h, pCw3l, rb3,
                                                    pRech, pRecl, pw, pb, out);
}

// round 10
// speedup vs baseline: 1.0146x; 1.0146x over previous
#include <cuda_runtime.h>
#include <cuda_bf16.h>
#include <math.h>
#include <stdint.h>

#define B_      1024
#define P_      11
#define C_      8
#define H_      512
#define T_      200
#define L_      2000
#define STRIDE_ 180
#define M_      (B_*P_*C_)

typedef unsigned long long u64;
typedef unsigned int u32;
typedef __nv_bfloat16 bf16;

// ---------------- scratch (device globals) ----------------
__device__ bf16 g_Hh[(size_t)M_ * 512];
__device__ bf16 g_Hl[(size_t)M_ * 512];
__device__ bf16 g_W1th[512 * 512];
__device__ bf16 g_W1tl[512 * 512];
__device__ bf16 g_W2th[256 * 512];
__device__ bf16 g_W2tl[256 * 512];
__device__ float g_patches[(size_t)M_ * T_];
__device__ bf16 g_rech[(size_t)B_ * L_ * 8];
__device__ bf16 g_recl[(size_t)B_ * L_ * 8];
__device__ bf16 g_r1h[(size_t)B_ * L_ * 32];
__device__ bf16 g_r1l[(size_t)B_ * L_ * 32];
__device__ bf16 g_r2h[(size_t)B_ * L_ * 16];
__device__ bf16 g_r2l[(size_t)B_ * L_ * 16];
__device__ bf16 g_cw1h[32 * 128];
__device__ bf16 g_cw1l[32 * 128];
__device__ bf16 g_w2h[16 * 480];
__device__ bf16 g_w2l[16 * 480];
__device__ bf16 g_cw3h[8 * 240];
__device__ bf16 g_cw3l[8 * 240];

__device__ __forceinline__ float gelu_erf(float x) {
    return 0.5f * x * (1.0f + erff(x * 0.7071067811865476f));
}

// ---------------- warp MMA primitives ----------------
__device__ __forceinline__ uint32_t smem_u32(const void* p) {
    uint32_t a;
    asm("{ .reg .u64 t; cvta.to.shared.u64 t, %1; cvt.u32.u64 %0, t; }" : "=r"(a) : "l"(p));
    return a;
}
__device__ __forceinline__ void ldsm_x4(u32& r0, u32& r1, u32& r2, u32& r3, u32 addr) {
    asm volatile("ldmatrix.sync.aligned.m8n8.x4.shared.b16 {%0,%1,%2,%3}, [%4];"
        : "=r"(r0), "=r"(r1), "=r"(r2), "=r"(r3) : "r"(addr));
}
__device__ __forceinline__ void ldsm_x2(u32& r0, u32& r1, u32 addr) {
    asm volatile("ldmatrix.sync.aligned.m8n8.x2.shared.b16 {%0,%1}, [%2];"
        : "=r"(r0), "=r"(r1) : "r"(addr));
}
__device__ __forceinline__ void mma_bf16(float* d, const u32* a, const u32* b) {
    asm volatile("mma.sync.aligned.m16n8k16.row.col.f32.bf16.bf16.f32 "
        "{%0,%1,%2,%3}, {%4,%5,%6,%7}, {%8,%9}, {%0,%1,%2,%3};"
        : "+f"(d[0]), "+f"(d[1]), "+f"(d[2]), "+f"(d[3])
        : "r"(a[0]), "r"(a[1]), "r"(a[2]), "r"(a[3]), "r"(b[0]), "r"(b[1]));
}
__device__ __forceinline__ void split_bf16(float v, bf16& h, bf16& l) {
    h = __float2bfloat16(v);
    l = __float2bfloat16(v - __bfloat162float(h));
}

// ================= prep kernels (weights only) =================
__global__ void transp_split_kernel(const float* __restrict__ W,
                                    bf16* __restrict__ th, bf16* __restrict__ tl,
                                    int Kdim, int Nsrc, int Npad)
{
    int idx = blockIdx.x * 256 + threadIdx.x;
    if (idx >= Npad * Kdim) return;
    int n = idx / Kdim, k = idx - n * Kdim;
    float f = (n < Nsrc) ? W[(size_t)k * Nsrc + n] : 0.0f;
    split_bf16(f, th[idx], tl[idx]);
}

__global__ void w1c_prep_kernel(const float* __restrict__ w,
                                bf16* __restrict__ wh, bf16* __restrict__ wl)
{
    int idx = blockIdx.x * 256 + threadIdx.x;
    if (idx >= 32 * 128) return;
    int co = idx >> 7, c = idx & 127;
    int ks = c >> 4, rem = c & 15;
    int tap = 2 * ks + (rem >> 3);
    int ic = rem & 7;
    float f = (tap < 15) ? w[((size_t)co * 8 + ic) * 15 + tap] : 0.0f;
    split_bf16(f, wh[idx], wl[idx]);
}

__global__ void w2_prep_kernel(const float* __restrict__ w,
                               bf16* __restrict__ wh, bf16* __restrict__ wl)
{
    int idx = blockIdx.x * 256 + threadIdx.x;
    if (idx >= 16 * 480) return;
    int co = idx / 480, c = idx - co * 480;
    int k = c >> 5, ic = c & 31;
    float f = w[((size_t)co * 32 + ic) * 15 + k];
    split_bf16(f, wh[idx], wl[idx]);
}

__global__ void w3c_prep_kernel(const float* __restrict__ w,
                                bf16* __restrict__ wh, bf16* __restrict__ wl)
{
    int idx = blockIdx.x * 256 + threadIdx.x;
    if (idx >= 8 * 240) return;
    int co = idx / 240, c = idx - co * 240;
    int k = c >> 4, ic = c & 15;
    float f = w[((size_t)co * 16 + ic) * 15 + k];
    split_bf16(f, wh[idx], wl[idx]);
}

// ================= HMMA GEMM, double-buffered k-pipeline =================
#define ASTR 40
#define A_ELE (128 * ASTR)   // elements per A buffer (per split)
#define B_ELE (64 * ASTR)
#define GEMM_SMEM ((2 * A_ELE * 2 + 2 * B_ELE * 2) * 2)  // 61440 bytes

template<bool A_FP32, bool GELU_SPLIT>
__global__ void __launch_bounds__(256, 2) gemm_hmma(
    const float* __restrict__ Af,
    const bf16* __restrict__ Ah, const bf16* __restrict__ Al,
    const bf16* __restrict__ Bh, const bf16* __restrict__ Bl,
    const float* __restrict__ bias, int Nvalid,
    bf16* __restrict__ outHh, bf16* __restrict__ outHl, float* __restrict__ outF)
{
    extern __shared__ __align__(16) char dynsm[];
    bf16* sAh = (bf16*)dynsm;             // [2][A_ELE]
    bf16* sAl = sAh + 2 * A_ELE;
    bf16* sBh = sAl + 2 * A_ELE;          // [2][B_ELE]
    bf16* sBl = sBh + 2 * B_ELE;

    const int tid  = threadIdx.x;
    const int lane = tid & 31;
    const int wid  = tid >> 5;
    const int wm   = wid & 3;
    const int wn   = wid >> 2;
    const int bm   = blockIdx.y * 128;
    const int bn   = blockIdx.x * 64;

    float acc[2][4][4];
#pragma unroll
    for (int i = 0; i < 2; i++)
#pragma unroll
        for (int j = 0; j < 4; j++)
#pragma unroll
            for (int q = 0; q < 4; q++) acc[i][j][q] = 0.0f;

    const int ar = tid >> 2;
    const int aq = (tid & 3) * 8;
    const size_t gA0 = (size_t)(bm + ar) * 512 + aq;
    const size_t gA1 = (size_t)(bm + ar + 64) * 512 + aq;
    const size_t gB0 = (size_t)(bn + ar) * 512 + aq;

    const u32 sbAh = smem_u32(sAh), sbAl = smem_u32(sAl);
    const u32 sbBh = smem_u32(sBh), sbBl = smem_u32(sBl);

    const int lrow = lane & 15;
    const int lhalf = (lane >> 4) * 8;
    const u32 aoffA0 = ((wm * 32 +      lrow) * ASTR + lhalf) * 2;
    const u32 aoffA1 = ((wm * 32 + 16 + lrow) * ASTR + lhalf) * 2;
    const u32 aoffB0 = ((wn * 32 +      lrow) * ASTR + lhalf) * 2;
    const u32 aoffB1 = ((wn * 32 + 16 + lrow) * ASTR + lhalf) * 2;

    uint4 pah0, pah1, pal0, pal1;
    float4 fa0, fa1, fb0, fb1;
    uint4 pbh, pbl;

    if (A_FP32) {
        fa0 = *(const float4*)(Af + gA0); fa1 = *(const float4*)(Af + gA0 + 4);
        fb0 = *(const float4*)(Af + gA1); fb1 = *(const float4*)(Af + gA1 + 4);
    } else {
        pah0 = *(const uint4*)(Ah + gA0); pah1 = *(const uint4*)(Ah + gA1);
        pal0 = *(const uint4*)(Al + gA0); pal1 = *(const uint4*)(Al + gA1);
    }
    pbh = *(const uint4*)(Bh + gB0); pbl = *(const uint4*)(Bl + gB0);

    const int sA0 = ar * ASTR + aq, sA1 = (ar + 64) * ASTR + aq, sB0 = ar * ASTR + aq;

    for (int kt = 0; kt < 16; kt++) {
        const int cur = kt & 1;
        const int aBuf = cur * A_ELE, bBuf = cur * B_ELE;

        // store prefetched tile kt into buf[cur]
        if (A_FP32) {
            float f0[8] = {fa0.x, fa0.y, fa0.z, fa0.w, fa1.x, fa1.y, fa1.z, fa1.w};
            float f1[8] = {fb0.x, fb0.y, fb0.z, fb0.w, fb1.x, fb1.y, fb1.z, fb1.w};
            unsigned short h0[8], l0[8], h1[8], l1[8];
#pragma unroll
            for (int j = 0; j < 8; j++) {
                bf16 h, l;
                split_bf16(f0[j], h, l);
                h0[j] = __bfloat16_as_ushort(h); l0[j] = __bfloat16_as_ushort(l);
                split_bf16(f1[j], h, l);
                h1[j] = __bfloat16_as_ushort(h); l1[j] = __bfloat16_as_ushort(l);
            }
            *(uint4*)(sAh + aBuf + sA0) = *(uint4*)h0; *(uint4*)(sAl + aBuf + sA0) = *(uint4*)l0;
            *(uint4*)(sAh + aBuf + sA1) = *(uint4*)h1; *(uint4*)(sAl + aBuf + sA1) = *(uint4*)l1;
        } else {
            *(uint4*)(sAh + aBuf + sA0) = pah0; *(uint4*)(sAh + aBuf + sA1) = pah1;
            *(uint4*)(sAl + aBuf + sA0) = pal0; *(uint4*)(sAl + aBuf + sA1) = pal1;
        }
        *(uint4*)(sBh + bBuf + sB0) = pbh; *(uint4*)(sBl + bBuf + sB0) = pbl;
        __syncthreads();   // single barrier per tile

        if (kt < 15) {
            int k0 = (kt + 1) * 32;
            if (A_FP32) {
                fa0 = *(const float4*)(Af + gA0 + k0); fa1 = *(const float4*)(Af + gA0 + k0 + 4);
                fb0 = *(const float4*)(Af + gA1 + k0); fb1 = *(const float4*)(Af + gA1 + k0 + 4);
            } else {
                pah0 = *(const uint4*)(Ah + gA0 + k0); pah1 = *(const uint4*)(Ah + gA1 + k0);
                pal0 = *(const uint4*)(Al + gA0 + k0); pal1 = *(const uint4*)(Al + gA1 + k0);
            }
            pbh = *(const uint4*)(Bh + gB0 + k0); pbl = *(const uint4*)(Bl + gB0 + k0);
        }

        const u32 aByte = (u32)(aBuf * 2), bByte = (u32)(bBuf * 2);
#pragma unroll
        for (int kk = 0; kk < 2; kk++) {
            const u32 kadd = kk * 32;
            u32 a_h[2][4], a_l[2][4];
            ldsm_x4(a_h[0][0], a_h[0][1], a_h[0][2], a_h[0][3], sbAh + aByte + aoffA0 + kadd);
            ldsm_x4(a_h[1][0], a_h[1][1], a_h[1][2], a_h[1][3], sbAh + aByte + aoffA1 + kadd);
            ldsm_x4(a_l[0][0], a_l[0][1], a_l[0][2], a_l[0][3], sbAl + aByte + aoffA0 + kadd);
            ldsm_x4(a_l[1][0], a_l[1][1], a_l[1][2], a_l[1][3], sbAl + aByte + aoffA1 + kadd);

            u32 t0, t1, t2, t3;
            u32 b_h[4][2], b_l[4][2];
            ldsm_x4(t0, t1, t2, t3, sbBh + bByte + aoffB0 + kadd);
            b_h[0][0] = t0; b_h[0][1] = t2; b_h[1][0] = t1; b_h[1][1] = t3;
            ldsm_x4(t0, t1, t2, t3, sbBh + bByte + aoffB1 + kadd);
            b_h[2][0] = t0; b_h[2][1] = t2; b_h[3][0] = t1; b_h[3][1] = t3;
            ldsm_x4(t0, t1, t2, t3, sbBl + bByte + aoffB0 + kadd);
            b_l[0][0] = t0; b_l[0][1] = t2; b_l[1][0] = t1; b_l[1][1] = t3;
            ldsm_x4(t0, t1, t2, t3, sbBl + bByte + aoffB1 + kadd);
            b_l[2][0] = t0; b_l[2][1] = t2; b_l[3][0] = t1; b_l[3][1] = t3;

#pragma unroll
            for (int s = 0; s < 3; s++) {
#pragma unroll
                for (int mi = 0; mi < 2; mi++)
#pragma unroll
                    for (int ni = 0; ni < 4; ni++) {
                        const u32* aa = (s == 2) ? a_l[mi] : a_h[mi];
                        const u32* bb = (s == 1) ? b_l[ni] : b_h[ni];
                        mma_bf16(acc[mi][ni], aa, bb);
                    }
            }
        }
        // no trailing sync: next iteration's stores target the other buffer
    }

    const int grp = lane >> 2;
    const int qc  = (lane & 3) * 2;
#pragma unroll
    for (int mi = 0; mi < 2; mi++) {
        const int r0 = bm + wm * 32 + mi * 16 + grp;
        const int r1 = r0 + 8;
#pragma unroll
        for (int ni = 0; ni < 4; ni++) {
            const int col = bn + wn * 32 + ni * 8 + qc;
            float bv0 = __ldg(&bias[col]), bv1 = __ldg(&bias[col + 1]);
            float v00 = acc[mi][ni][0] + bv0, v01 = acc[mi][ni][1] + bv1;
            float v10 = acc[mi][ni][2] + bv0, v11 = acc[mi][ni][3] + bv1;
            if (GELU_SPLIT) {
                v00 = gelu_erf(v00); v01 = gelu_erf(v01);
                v10 = gelu_erf(v10); v11 = gelu_erf(v11);
                bf16 h0, h1, l0, l1;
                split_bf16(v00, h0, l0); split_bf16(v01, h1, l1);
                size_t i0 = (size_t)r0 * 256 + (col >> 1);
                reinterpret_cast<__nv_bfloat162*>(outHh)[i0] = __halves2bfloat162(h0, h1);
                reinterpret_cast<__nv_bfloat162*>(outHl)[i0] = __halves2bfloat162(l0, l1);
                split_bf16(v10, h0, l0); split_bf16(v11, h1, l1);
                size_t i1 = (size_t)r1 * 256 + (col >> 1);
                reinterpret_cast<__nv_bfloat162*>(outHh)[i1] = __halves2bfloat162(h0, h1);
                reinterpret_cast<__nv_bfloat162*>(outHl)[i1] = __halves2bfloat162(l0, l1);
            } else {
                if (col < Nvalid) {
                    *(float2*)(outF + (size_t)r0 * Nvalid + col) = make_float2(v00, v01);
                    *(float2*)(outF + (size_t)r1 * Nvalid + col) = make_float2(v10, v11);
                }
            }
        }
    }
}

// ================= overlap-add -> rec bf16 split [b][l][8] =================
__global__ void overlap_add_v3(const float* __restrict__ patches,
                               bf16* __restrict__ rech, bf16* __restrict__ recl)
{
    const int b  = blockIdx.y;
    const int l  = blockIdx.x * 256 + threadIdx.x;
    if (l >= L_) return;

    int i_lo = l - (T_ - 1);
    i_lo = (i_lo > 0) ? (i_lo + STRIDE_ - 1) / STRIDE_ : 0;
    int i_hi = l / STRIDE_;
    if (i_hi > P_ - 1) i_hi = P_ - 1;

    int np = 0, pi[2], pt[2];
    float wv[2], ws = 0.0f;
    for (int i = i_lo; i <= i_hi; i++) {
        int t = l - i * STRIDE_;
        float w;
        if (t < 50)        w = (float)t * (1.0f / 49.0f);
        else if (t >= 150) w = (float)(199 - t) * (1.0f / 49.0f);
        else               w = 1.0f;
        pi[np] = i; pt[np] = t; wv[np] = w; ws += w; np++;
    }
    float ews = fmaxf(ws, 1e-8f);

    unsigned short hh[8], ll[8];
#pragma unroll
    for (int c = 0; c < 8; c++) {
        float v = 0.0f;
        for (int j = 0; j < np; j++)
            v += patches[(((size_t)b * P_ + pi[j]) * C_ + c) * T_ + pt[j]] * wv[j];
        v = v / ews;
        bf16 h, lo; split_bf16(v, h, lo);
        hh[c] = __bfloat16_as_ushort(h);
        ll[c] = __bfloat16_as_ushort(lo);
    }
    size_t o = ((size_t)b * L_ + l) * 8;
    *(uint4*)(rech + o) = *(uint4*)hh;
    *(uint4*)(recl + o) = *(uint4*)ll;
}

// ================= conv1: 8->32 k15, HMMA =================
#define C1XSTR 40
#define C1WSTR 136
__global__ void __launch_bounds__(256) conv1_hmma(
    const bf16* __restrict__ rech, const bf16* __restrict__ recl,
    const bf16* __restrict__ wh, const bf16* __restrict__ wl,
    const float* __restrict__ bias,
    bf16* __restrict__ r1h, bf16* __restrict__ r1l)
{
    __shared__ __align__(16) bf16 sXh[143 * C1XSTR];
    __shared__ __align__(16) bf16 sXl[143 * C1XSTR];
    __shared__ __align__(16) bf16 sWh[32 * C1WSTR];
    __shared__ __align__(16) bf16 sWl[32 * C1WSTR];

    const int tid  = threadIdx.x;
    const int lane = tid & 31;
    const int wm   = tid >> 5;
    const int b    = blockIdx.y;

    for (int i = tid; i < 32 * 64; i += 256) {
        int r = i >> 6, q = i & 63;
        ((u32*)sWh)[r * (C1WSTR/2) + q] = ((const u32*)wh)[r * 64 + q];
        ((u32*)sWl)[r * (C1WSTR/2) + q] = ((const u32*)wl)[r * 64 + q];
    }

    const u32 sbXh = smem_u32(sXh), sbXl = smem_u32(sXl);
    const u32 sbWh = smem_u32(sWh), sbWl = smem_u32(sWl);
    const int lrow = lane & 15;
    const int lhalf = (lane >> 4) * 8;
    const int grp = lane >> 2, qc = (lane & 3) * 2;

    for (int tile = 0; tile < 2; tile++) {
        const int t0 = blockIdx.x * 256 + tile * 128;
        __syncthreads();
        for (int i = tid; i < 143 * 2; i += 256) {
            int r = i >> 1, half = i & 1;
            int gp = t0 + r - 7 + half;
            uint4 vh = make_uint4(0,0,0,0), vl = vh;
            if (gp >= 0 && gp < L_) {
                size_t o = ((size_t)b * L_ + gp) * 8;
                vh = *(const uint4*)(rech + o);
                vl = *(const uint4*)(recl + o);
            }
            *(uint4*)(sXh + r * C1XSTR + half * 8) = vh;
            *(uint4*)(sXl + r * C1XSTR + half * 8) = vl;
        }
        __syncthreads();

        float a0[4][4], a1[4][4], a2[4][4];
#pragma unroll
        for (int ni = 0; ni < 4; ni++)
#pragma unroll
            for (int q = 0; q < 4; q++) { a0[ni][q] = 0.f; a1[ni][q] = 0.f; a2[ni][q] = 0.f; }

#pragma unroll
        for (int k = 0; k < 8; k++) {
            u32 aadd = (u32)((wm * 16 + lrow + 2 * k) * C1XSTR + lhalf) * 2;
            u32 ah[4], al[4];
            ldsm_x4(ah[0], ah[1], ah[2], ah[3], sbXh + aadd);
            ldsm_x4(al[0], al[1], al[2], al[3], sbXl + aadd);

            u32 t0r, t1r, t2r, t3r;
            u32 bh[4][2], bl[4][2];
#pragma unroll
            for (int na2 = 0; na2 < 2; na2++) {
                u32 badd = (u32)((na2 * 16 + lrow) * C1WSTR + k * 16 + lhalf) * 2;
                ldsm_x4(t0r, t1r, t2r, t3r, sbWh + badd);
                bh[na2*2][0] = t0r; bh[na2*2][1] = t2r;
                bh[na2*2+1][0] = t1r; bh[na2*2+1][1] = t3r;
                ldsm_x4(t0r, t1r, t2r, t3r, sbWl + badd);
                bl[na2*2][0] = t0r; bl[na2*2][1] = t2r;
                bl[na2*2+1][0] = t1r; bl[na2*2+1][1] = t3r;
            }
#pragma unroll
            for (int ni = 0; ni < 4; ni++) mma_bf16(a0[ni], ah, bh[ni]);
#pragma unroll
            for (int ni = 0; ni < 4; ni++) mma_bf16(a1[ni], ah, bl[ni]);
#pragma unroll
            for (int ni = 0; ni < 4; ni++) mma_bf16(a2[ni], al, bh[ni]);
        }
        __syncthreads();

        u32* stgh = (u32*)sXh;
        u32* stgl = (u32*)sXl;
#pragma unroll
        for (int ni = 0; ni < 4; ni++) {
            float acc[4];
#pragma unroll
            for (int q = 0; q < 4; q++) acc[q] = a0[ni][q] + a1[ni][q] + a2[ni][q];
            int ch = ni * 8 + qc;
            float bv0 = __ldg(&bias[ch]), bv1 = __ldg(&bias[ch + 1]);
            int p0 = wm * 16 + grp, p1 = p0 + 8;
            float v00 = gelu_erf(acc[0] + bv0), v01 = gelu_erf(acc[1] + bv1);
            float v10 = gelu_erf(acc[2] + bv0), v11 = gelu_erf(acc[3] + bv1);
            bf16 h0, h1, l0, l1;
            split_bf16(v00, h0, l0); split_bf16(v01, h1, l1);
            __nv_bfloat162 th = __halves2bfloat162(h0, h1), tl = __halves2bfloat162(l0, l1);
            stgh[p0 * 17 + ni * 4 + (lane & 3)] = *(u32*)&th;
            stgl[p0 * 17 + ni * 4 + (lane & 3)] = *(u32*)&tl;
            split_bf16(v10, h0, l0); split_bf16(v11, h1, l1);
            th = __halves2bfloat162(h0, h1); tl = __halves2bfloat162(l0, l1);
            stgh[p1 * 17 + ni * 4 + (lane & 3)] = *(u32*)&th;
            stgl[p1 * 17 + ni * 4 + (lane & 3)] = *(u32*)&tl;
        }
        __syncthreads();
        for (int i = tid; i < 128 * 16; i += 256) {
            int p = i >> 4, q = i & 15;
            int l = t0 + p;
            if (l < L_) {
                size_t o = ((size_t)b * L_ + l) * 16 + q;
                ((u32*)r1h)[o] = stgh[p * 17 + q];
                ((u32*)r1l)[o] = stgl[p * 17 + q];
            }
        }
    }
}

// ================= conv2: 32->16 k15, HMMA =================
#define X2STR 40
#define W2STR 488
__global__ void __launch_bounds__(256) conv2_hmma(
    const bf16* __restrict__ r1h, const bf16* __restrict__ r1l,
    const bf16* __restrict__ wh, const bf16* __restrict__ wl,
    const float* __restrict__ bias,
    bf16* __restrict__ r2h, bf16* __restrict__ r2l)
{
    __shared__ __align__(16) bf16 sXh[144 * X2STR];
    __shared__ __align__(16) bf16 sXl[144 * X2STR];
    __shared__ __align__(16) bf16 sWh[16 * W2STR];
    __shared__ __align__(16) bf16 sWl[16 * W2STR];

    const int tid  = threadIdx.x;
    const int lane = tid & 31;
    const int wm   = tid >> 5;
    const int b    = blockIdx.y;

    for (int i = tid; i < 16 * 240; i += 256) {
        int r = i / 240, c = i - r * 240;
        ((u32*)sWh)[r * (W2STR/2) + c] = ((const u32*)wh)[r * 240 + c];
        ((u32*)sWl)[r * (W2STR/2) + c] = ((const u32*)wl)[r * 240 + c];
    }

    const u32 sbXh = smem_u32(sXh), sbXl = smem_u32(sXl);
    const u32 sbWh = smem_u32(sWh), sbWl = smem_u32(sWl);
    const int lrow = lane & 15;
    const int lhalf = (lane >> 4) * 8;
    const u32 boff  = sbWh + ((lane & 15) * W2STR + lhalf) * 2;
    const u32 boffl = sbWl + ((lane & 15) * W2STR + lhalf) * 2;
    const int grp = lane >> 2, qc = (lane & 3) * 2;

    for (int tile = 0; tile < 2; tile++) {
        const int t0 = blockIdx.x * 256 + tile * 128;
        __syncthreads();
        for (int i = tid; i < 144 * 4; i += 256) {
            int r = i >> 2, q = i & 3;
            int gp = t0 + r - 8;
            uint4 vh = make_uint4(0,0,0,0), vl = vh;
            if (gp >= 0 && gp < L_) {
                size_t o = ((size_t)b * L_ + gp) * 32 + q * 8;
                vh = *(const uint4*)(r1h + o);
                vl = *(const uint4*)(r1l + o);
            }
            *(uint4*)(sXh + r * X2STR + q * 8) = vh;
            *(uint4*)(sXl + r * X2STR + q * 8) = vl;
        }
        __syncthreads();

        float a0[2][4], a1[2][4], a2[2][4];
#pragma unroll
        for (int ni = 0; ni < 2; ni++)
#pragma unroll
            for (int q = 0; q < 4; q++) { a0[ni][q] = 0.f; a1[ni][q] = 0.f; a2[ni][q] = 0.f; }

#pragma unroll 2
        for (int ks = 0; ks < 30; ks++) {
            const int k   = ks >> 1;
            const int icb = (ks & 1) * 16;
            const u32 aadd = (u32)((wm * 16 + lrow + k + 1) * X2STR + icb + lhalf) * 2;

            u32 ah[4], al[4];
            ldsm_x4(ah[0], ah[1], ah[2], ah[3], sbXh + aadd);
            ldsm_x4(al[0], al[1], al[2], al[3], sbXl + aadd);

            u32 t0r, t1r, t2r, t3r;
            u32 bh[2][2], bl[2][2];
            ldsm_x4(t0r, t1r, t2r, t3r, boff + ks * 32);
            bh[0][0] = t0r; bh[0][1] = t2r; bh[1][0] = t1r; bh[1][1] = t3r;
            ldsm_x4(t0r, t1r, t2r, t3r, boffl + ks * 32);
            bl[0][0] = t0r; bl[0][1] = t2r; bl[1][0] = t1r; bl[1][1] = t3r;

#pragma unroll
            for (int ni = 0; ni < 2; ni++) mma_bf16(a0[ni], ah, bh[ni]);
#pragma unroll
            for (int ni = 0; ni < 2; ni++) mma_bf16(a1[ni], ah, bl[ni]);
#pragma unroll
            for (int ni = 0; ni < 2; ni++) mma_bf16(a2[ni], al, bh[ni]);
        }
        __syncthreads();

        u32* stgh = (u32*)sXh;
        u32* stgl = (u32*)sXl;
#pragma unroll
        for (int ni = 0; ni < 2; ni++) {
            float acc[4];
#pragma unroll
            for (int q = 0; q < 4; q++) acc[q] = a0[ni][q] + a1[ni][q] + a2[ni][q];
            int ch = ni * 8 + qc;
            float bv0 = __ldg(&bias[ch]), bv1 = __ldg(&bias[ch + 1]);
            int p0 = wm * 16 + grp, p1 = p0 + 8;
            float v00 = gelu_erf(acc[0] + bv0), v01 = gelu_erf(acc[1] + bv1);
            float v10 = gelu_erf(acc[2] + bv0), v11 = gelu_erf(acc[3] + bv1);
            bf16 h0, h1, l0, l1;
            split_bf16(v00, h0, l0); split_bf16(v01, h1, l1);
            __nv_bfloat162 th = __halves2bfloat162(h0, h1), tl = __halves2bfloat162(l0, l1);
            stgh[p0 * 9 + ni * 4 + (lane & 3)] = *(u32*)&th;
            stgl[p0 * 9 + ni * 4 + (lane & 3)] = *(u32*)&tl;
            split_bf16(v10, h0, l0); split_bf16(v11, h1, l1);
            th = __halves2bfloat162(h0, h1); tl = __halves2bfloat162(l0, l1);
            stgh[p1 * 9 + ni * 4 + (lane & 3)] = *(u32*)&th;
            stgl[p1 * 9 + ni * 4 + (lane & 3)] = *(u32*)&tl;
        }
        __syncthreads();
        for (int i = tid; i < 128 * 8; i += 256) {
            int p = i >> 3, q = i & 7;
            int l = t0 + p;
            if (l < L_) {
                size_t o = ((size_t)b * L_ + l) * 8 + q;
                ((u32*)r2h)[o] = stgh[p * 9 + q];
                ((u32*)r2l)[o] = stgl[p * 9 + q];
            }
        }
    }
}

// ================= conv3: 16->8 k15 HMMA + residual + pointwise =================
#define X3STR 40
#define W3STR 248
__global__ void __launch_bounds__(256) conv3_hmma(
    const bf16* __restrict__ r2h, const bf16* __restrict__ r2l,
    const bf16* __restrict__ wh, const bf16* __restrict__ wl,
    const float* __restrict__ bias,
    const bf16* __restrict__ rech, const bf16* __restrict__ recl,
    const float* __restrict__ pw, const float* __restrict__ pb,
    float* __restrict__ out)
{
    __shared__ __align__(16) bf16 sXh[143 * X3STR];
    __shared__ __align__(16) bf16 sXl[143 * X3STR];
    __shared__ __align__(16) bf16 sWh[8 * W3STR];
    __shared__ __align__(16) bf16 sWl[8 * W3STR];
    __shared__ float sF[128 * 9];

    const int tid  = threadIdx.x;
    const int lane = tid & 31;
    const int wm   = tid >> 5;
    const int b    = blockIdx.y;

    for (int i = tid; i < 8 * 120; i += 256) {
        int r = i / 120, c = i - r * 120;
        ((u32*)sWh)[r * (W3STR/2) + c] = ((const u32*)wh)[r * 120 + c];
        ((u32*)sWl)[r * (W3STR/2) + c] = ((const u32*)wl)[r * 120 + c];
    }

    const u32 sbXh = smem_u32(sXh), sbXl = smem_u32(sXl);
    const u32 sbWh = smem_u32(sWh), sbWl = smem_u32(sWl);
    const int lrow = lane & 15;
    const int lhalf = (lane >> 4) * 8;
    const u32 bbase = ((lane & 7) * W3STR + ((lane >> 3) & 1) * 8) * 2;
    const int grp = lane >> 2, qc = (lane & 3) * 2;

    for (int tile = 0; tile < 2; tile++) {
        const int t0 = blockIdx.x * 256 + tile * 128;
        __syncthreads();
        for (int i = tid; i < 143 * 2; i += 256) {
            int r = i >> 1, q = i & 1;
            int gp = t0 + r - 7;
            uint4 vh = make_uint4(0,0,0,0), vl = vh;
            if (gp >= 0 && gp < L_) {
                size_t o = ((size_t)b * L_ + gp) * 16 + q * 8;
                vh = *(const uint4*)(r2h + o);
                vl = *(const uint4*)(r2l + o);
            }
            *(uint4*)(sXh + r * X3STR + q * 8) = vh;
            *(uint4*)(sXl + r * X3STR + q * 8) = vl;
        }
        __syncthreads();

        float a0[4] = {0,0,0,0}, a1[4] = {0,0,0,0}, a2[4] = {0,0,0,0};
#pragma unroll
        for (int k = 0; k < 15; k++) {
            u32 aadd = (u32)((wm * 16 + lrow + k) * X3STR + lhalf) * 2;
            u32 ah[4], al[4];
            ldsm_x4(ah[0], ah[1], ah[2], ah[3], sbXh + aadd);
            ldsm_x4(al[0], al[1], al[2], al[3], sbXl + aadd);
            u32 bh[2], bl[2];
            ldsm_x2(bh[0], bh[1], sbWh + bbase + k * 32);
            ldsm_x2(bl[0], bl[1], sbWl + bbase + k * 32);
            mma_bf16(a0, ah, bh);
            mma_bf16(a1, ah, bl);
            mma_bf16(a2, al, bh);
        }
        __syncthreads();

        {
            float acc[4];
#pragma unroll
            for (int q = 0; q < 4; q++) acc[q] = a0[q] + a1[q] + a2[q];
            float bv0 = __ldg(&bias[qc]), bv1 = __ldg(&bias[qc + 1]);
            int p0 = wm * 16 + grp, p1 = p0 + 8;
            sF[p0 * 9 + qc]     = acc[0] + bv0;
            sF[p0 * 9 + qc + 1] = acc[1] + bv1;
            sF[p1 * 9 + qc]     = acc[2] + bv0;
            sF[p1 * 9 + qc + 1] = acc[3] + bv1;
        }
        __syncthreads();

        if (tid < 128) {
            int l = t0 + tid;
            if (l < L_) {
                size_t ro = ((size_t)b * L_ + l) * 8;
                uint4 vh = *(const uint4*)(rech + ro);
                uint4 vl = *(const uint4*)(recl + ro);
                const unsigned short* hs = (const unsigned short*)&vh;
                const unsigned short* ls = (const unsigned short*)&vl;
                float resid[8];
#pragma unroll
                for (int c = 0; c < 8; c++) {
                    float rv = __bfloat162float(__ushort_as_bfloat16(hs[c]))
                             + __bfloat162float(__ushort_as_bfloat16(ls[c]));
                    resid[c] = rv + sF[tid * 9 + c];
                }
#pragma unroll
                for (int o = 0; o < 8; o++) {
                    float v = __ldg(&pb[o]);
#pragma unroll
                    for (int c = 0; c < 8; c++)
                        v += __ldg(&pw[o * C_ + c]) * resid[c];
                    out[((size_t)b * C_ + o) * L_ + l] = v;
                }
            }
        }
    }
}

// ---------------- launcher ----------------
extern "C" void kernel_launch(void* const* d_in, const int* in_sizes, int n_in,
                              void* d_out, int out_size)
{
    const float* X   = (const float*)d_in[0];
    const float* W1  = (const float*)d_in[1];
    const float* b1  = (const float*)d_in[2];
    const float* W2  = (const float*)d_in[3];
    const float* b2  = (const float*)d_in[4];
    const float* rw1 = (const float*)d_in[5];
    const float* rb1 = (const float*)d_in[6];
    const float* rw2 = (const float*)d_in[7];
    const float* rb2 = (const float*)d_in[8];
    const float* rw3 = (const float*)d_in[9];
    const float* rb3 = (const float*)d_in[10];
    const float* pw  = (const float*)d_in[11];
    const float* pb  = (const float*)d_in[12];
    float* out = (float*)d_out;

    bf16 *pHh, *pHl, *pW1th, *pW1tl, *pW2th, *pW2tl;
    bf16 *pRech, *pRecl, *pR1h, *pR1l, *pR2h, *pR2l;
    bf16 *pCw1h, *pCw1l, *pW2h, *pW2l, *pCw3h, *pCw3l;
    float *pPatches;
    cudaGetSymbolAddress((void**)&pHh,   g_Hh);
    cudaGetSymbolAddress((void**)&pHl,   g_Hl);
    cudaGetSymbolAddress((void**)&pW1th, g_W1th);
    cudaGetSymbolAddress((void**)&pW1tl, g_W1tl);
    cudaGetSymbolAddress((void**)&pW2th, g_W2th);
    cudaGetSymbolAddress((void**)&pW2tl, g_W2tl);
    cudaGetSymbolAddress((void**)&pPatches, g_patches);
    cudaGetSymbolAddress((void**)&pRech, g_rech);
    cudaGetSymbolAddress((void**)&pRecl, g_recl);
    cudaGetSymbolAddress((void**)&pR1h,  g_r1h);
    cudaGetSymbolAddress((void**)&pR1l,  g_r1l);
    cudaGetSymbolAddress((void**)&pR2h,  g_r2h);
    cudaGetSymbolAddress((void**)&pR2l,  g_r2l);
    cudaGetSymbolAddress((void**)&pCw1h, g_cw1h);
    cudaGetSymbolAddress((void**)&pCw1l, g_cw1l);
    cudaGetSymbolAddress((void**)&pW2h,  g_w2h);
    cudaGetSymbolAddress((void**)&pW2l,  g_w2l);
    cudaGetSymbolAddress((void**)&pCw3h, g_cw3h);
    cudaGetSymbolAddress((void**)&pCw3l, g_cw3l);

    cudaFuncSetAttribute(gemm_hmma<true,  true>,
                         cudaFuncAttributeMaxDynamicSharedMemorySize, GEMM_SMEM);
    cudaFuncSetAttribute(gemm_hmma<false, false>,
                         cudaFuncAttributeMaxDynamicSharedMemorySize, GEMM_SMEM);

    // launch order keeps gemm1 at slot 4 (the ncu capture slot)
    transp_split_kernel<<<(512*512 + 255) / 256, 256>>>(W1, pW1th, pW1tl, 512, 512, 512);  // 1
    transp_split_kernel<<<(256*512 + 255) / 256, 256>>>(W2, pW2th, pW2tl, 512, 200, 256);  // 2
    w1c_prep_kernel<<<(32*128 + 255) / 256, 256>>>(rw1, pCw1h, pCw1l);                     // 3

    // 4: GEMM1 -- Hh/Hl = split(GELU(X @ W1 + b1))
    gemm_hmma<true, true><<<dim3(8, M_ / 128), 256, GEMM_SMEM>>>(
        X, nullptr, nullptr, pW1th, pW1tl, b1, 512, pHh, pHl, nullptr);

    w2_prep_kernel<<<(16*480 + 255) / 256, 256>>>(rw2, pW2h, pW2l);                        // 5
    w3c_prep_kernel<<<(8*240 + 255) / 256, 256>>>(rw3, pCw3h, pCw3l);                      // 6

    // 7: GEMM2 -- patches = H @ W2 + b2
    gemm_hmma<false, false><<<dim3(4, M_ / 128), 256, GEMM_SMEM>>>(
        nullptr, pHh, pHl, pW2th, pW2tl, b2, 200, nullptr, nullptr, pPatches);

    // 8: overlap-add
    overlap_add_v3<<<dim3((L_ + 255) / 256, B_), 256>>>(pPatches, pRech, pRecl);

    // 9-11: convs
    conv1_hmma<<<dim3((L_ + 255) / 256, B_), 256>>>(pRech, pRecl, pCw1h, pCw1l, rb1, pR1h, pR1l);
    conv2_hmma<<<dim3((L_ + 255) / 256, B_), 256>>>(pR1h, pR1l, pW2h, pW2l, rb2, pR2h, pR2l);
    conv3_hmma<<<dim3((L_ + 255) / 256, B_), 256>>>(pR2h, pR2l, pCw3h, pCw3l, rb3,
                                                    pRech, pRecl, pw, pb, out);
}

// round 11
// speedup vs baseline: 1.0696x; 1.0542x over previous
#include <cuda_runtime.h>
#include <cuda_bf16.h>
#include <math.h>
#include <stdint.h>

#define B_      1024
#define P_      11
#define C_      8
#define H_      512
#define T_      200
#define L_      2000
#define STRIDE_ 180
#define M_      (B_*P_*C_)

typedef unsigned long long u64;
typedef unsigned int u32;
typedef __nv_bfloat16 bf16;

// ---------------- scratch (device globals) ----------------
__device__ bf16 g_Hh[(size_t)M_ * 512];
__device__ bf16 g_Hl[(size_t)M_ * 512];
__device__ bf16 g_W1th[512 * 512];
__device__ bf16 g_W1tl[512 * 512];
__device__ bf16 g_W2th[256 * 512];
__device__ bf16 g_W2tl[256 * 512];
__device__ float g_patches[(size_t)M_ * T_];
__device__ bf16 g_rech[(size_t)B_ * L_ * 8];
__device__ bf16 g_recl[(size_t)B_ * L_ * 8];
__device__ bf16 g_r1h[(size_t)B_ * L_ * 32];
__device__ bf16 g_r1l[(size_t)B_ * L_ * 32];
__device__ bf16 g_r2h[(size_t)B_ * L_ * 16];
__device__ bf16 g_r2l[(size_t)B_ * L_ * 16];
__device__ bf16 g_cw1h[32 * 128];
__device__ bf16 g_cw1l[32 * 128];
__device__ bf16 g_w2h[16 * 480];
__device__ bf16 g_w2l[16 * 480];
__device__ bf16 g_cw3h[8 * 240];
__device__ bf16 g_cw3l[8 * 240];

__device__ __forceinline__ float gelu_erf(float x) {
    return 0.5f * x * (1.0f + erff(x * 0.7071067811865476f));
}

// ---------------- warp MMA primitives ----------------
__device__ __forceinline__ uint32_t smem_u32(const void* p) {
    uint32_t a;
    asm("{ .reg .u64 t; cvta.to.shared.u64 t, %1; cvt.u32.u64 %0, t; }" : "=r"(a) : "l"(p));
    return a;
}
__device__ __forceinline__ void ldsm_x4(u32& r0, u32& r1, u32& r2, u32& r3, u32 addr) {
    asm volatile("ldmatrix.sync.aligned.m8n8.x4.shared.b16 {%0,%1,%2,%3}, [%4];"
        : "=r"(r0), "=r"(r1), "=r"(r2), "=r"(r3) : "r"(addr));
}
__device__ __forceinline__ void ldsm_x2(u32& r0, u32& r1, u32 addr) {
    asm volatile("ldmatrix.sync.aligned.m8n8.x2.shared.b16 {%0,%1}, [%2];"
        : "=r"(r0), "=r"(r1) : "r"(addr));
}
__device__ __forceinline__ void mma_bf16(float* d, const u32* a, const u32* b) {
    asm volatile("mma.sync.aligned.m16n8k16.row.col.f32.bf16.bf16.f32 "
        "{%0,%1,%2,%3}, {%4,%5,%6,%7}, {%8,%9}, {%0,%1,%2,%3};"
        : "+f"(d[0]), "+f"(d[1]), "+f"(d[2]), "+f"(d[3])
        : "r"(a[0]), "r"(a[1]), "r"(a[2]), "r"(a[3]), "r"(b[0]), "r"(b[1]));
}
__device__ __forceinline__ void split_bf16(float v, bf16& h, bf16& l) {
    h = __float2bfloat16(v);
    l = __float2bfloat16(v - __bfloat162float(h));
}

// ================= prep kernels (weights only) =================
__global__ void transp_split_kernel(const float* __restrict__ W,
                                    bf16* __restrict__ th, bf16* __restrict__ tl,
                                    int Kdim, int Nsrc, int Npad)
{
    int idx = blockIdx.x * 256 + threadIdx.x;
    if (idx >= Npad * Kdim) return;
    int n = idx / Kdim, k = idx - n * Kdim;
    float f = (n < Nsrc) ? W[(size_t)k * Nsrc + n] : 0.0f;
    split_bf16(f, th[idx], tl[idx]);
}

__global__ void w1c_prep_kernel(const float* __restrict__ w,
                                bf16* __restrict__ wh, bf16* __restrict__ wl)
{
    int idx = blockIdx.x * 256 + threadIdx.x;
    if (idx >= 32 * 128) return;
    int co = idx >> 7, c = idx & 127;
    int ks = c >> 4, rem = c & 15;
    int tap = 2 * ks + (rem >> 3);
    int ic = rem & 7;
    float f = (tap < 15) ? w[((size_t)co * 8 + ic) * 15 + tap] : 0.0f;
    split_bf16(f, wh[idx], wl[idx]);
}

__global__ void w2_prep_kernel(const float* __restrict__ w,
                               bf16* __restrict__ wh, bf16* __restrict__ wl)
{
    int idx = blockIdx.x * 256 + threadIdx.x;
    if (idx >= 16 * 480) return;
    int co = idx / 480, c = idx - co * 480;
    int k = c >> 5, ic = c & 31;
    float f = w[((size_t)co * 32 + ic) * 15 + k];
    split_bf16(f, wh[idx], wl[idx]);
}

__global__ void w3c_prep_kernel(const float* __restrict__ w,
                                bf16* __restrict__ wh, bf16* __restrict__ wl)
{
    int idx = blockIdx.x * 256 + threadIdx.x;
    if (idx >= 8 * 240) return;
    int co = idx / 240, c = idx - co * 240;
    int k = c >> 4, ic = c & 15;
    float f = w[((size_t)co * 16 + ic) * 15 + k];
    split_bf16(f, wh[idx], wl[idx]);
}

// ================= HMMA GEMM (unchanged from R10) =================
#define ASTR 40
#define A_ELE (128 * ASTR)
#define B_ELE (64 * ASTR)
#define GEMM_SMEM ((2 * A_ELE * 2 + 2 * B_ELE * 2) * 2)

template<bool A_FP32, bool GELU_SPLIT>
__global__ void __launch_bounds__(256, 2) gemm_hmma(
    const float* __restrict__ Af,
    const bf16* __restrict__ Ah, const bf16* __restrict__ Al,
    const bf16* __restrict__ Bh, const bf16* __restrict__ Bl,
    const float* __restrict__ bias, int Nvalid,
    bf16* __restrict__ outHh, bf16* __restrict__ outHl, float* __restrict__ outF)
{
    extern __shared__ __align__(16) char dynsm[];
    bf16* sAh = (bf16*)dynsm;
    bf16* sAl = sAh + 2 * A_ELE;
    bf16* sBh = sAl + 2 * A_ELE;
    bf16* sBl = sBh + 2 * B_ELE;

    const int tid  = threadIdx.x;
    const int lane = tid & 31;
    const int wid  = tid >> 5;
    const int wm   = wid & 3;
    const int wn   = wid >> 2;
    const int bm   = blockIdx.y * 128;
    const int bn   = blockIdx.x * 64;

    float acc[2][4][4];
#pragma unroll
    for (int i = 0; i < 2; i++)
#pragma unroll
        for (int j = 0; j < 4; j++)
#pragma unroll
            for (int q = 0; q < 4; q++) acc[i][j][q] = 0.0f;

    const int ar = tid >> 2;
    const int aq = (tid & 3) * 8;
    const size_t gA0 = (size_t)(bm + ar) * 512 + aq;
    const size_t gA1 = (size_t)(bm + ar + 64) * 512 + aq;
    const size_t gB0 = (size_t)(bn + ar) * 512 + aq;

    const u32 sbAh = smem_u32(sAh), sbAl = smem_u32(sAl);
    const u32 sbBh = smem_u32(sBh), sbBl = smem_u32(sBl);

    const int lrow = lane & 15;
    const int lhalf = (lane >> 4) * 8;
    const u32 aoffA0 = ((wm * 32 +      lrow) * ASTR + lhalf) * 2;
    const u32 aoffA1 = ((wm * 32 + 16 + lrow) * ASTR + lhalf) * 2;
    const u32 aoffB0 = ((wn * 32 +      lrow) * ASTR + lhalf) * 2;
    const u32 aoffB1 = ((wn * 32 + 16 + lrow) * ASTR + lhalf) * 2;

    uint4 pah0, pah1, pal0, pal1;
    float4 fa0, fa1, fb0, fb1;
    uint4 pbh, pbl;

    if (A_FP32) {
        fa0 = *(const float4*)(Af + gA0); fa1 = *(const float4*)(Af + gA0 + 4);
        fb0 = *(const float4*)(Af + gA1); fb1 = *(const float4*)(Af + gA1 + 4);
    } else {
        pah0 = *(const uint4*)(Ah + gA0); pah1 = *(const uint4*)(Ah + gA1);
        pal0 = *(const uint4*)(Al + gA0); pal1 = *(const uint4*)(Al + gA1);
    }
    pbh = *(const uint4*)(Bh + gB0); pbl = *(const uint4*)(Bl + gB0);

    const int sA0 = ar * ASTR + aq, sA1 = (ar + 64) * ASTR + aq, sB0 = ar * ASTR + aq;

    for (int kt = 0; kt < 16; kt++) {
        const int cur = kt & 1;
        const int aBuf = cur * A_ELE, bBuf = cur * B_ELE;

        if (A_FP32) {
            float f0[8] = {fa0.x, fa0.y, fa0.z, fa0.w, fa1.x, fa1.y, fa1.z, fa1.w};
            float f1[8] = {fb0.x, fb0.y, fb0.z, fb0.w, fb1.x, fb1.y, fb1.z, fb1.w};
            unsigned short h0[8], l0[8], h1[8], l1[8];
#pragma unroll
            for (int j = 0; j < 8; j++) {
                bf16 h, l;
                split_bf16(f0[j], h, l);
                h0[j] = __bfloat16_as_ushort(h); l0[j] = __bfloat16_as_ushort(l);
                split_bf16(f1[j], h, l);
                h1[j] = __bfloat16_as_ushort(h); l1[j] = __bfloat16_as_ushort(l);
            }
            *(uint4*)(sAh + aBuf + sA0) = *(uint4*)h0; *(uint4*)(sAl + aBuf + sA0) = *(uint4*)l0;
            *(uint4*)(sAh + aBuf + sA1) = *(uint4*)h1; *(uint4*)(sAl + aBuf + sA1) = *(uint4*)l1;
        } else {
            *(uint4*)(sAh + aBuf + sA0) = pah0; *(uint4*)(sAh + aBuf + sA1) = pah1;
            *(uint4*)(sAl + aBuf + sA0) = pal0; *(uint4*)(sAl + aBuf + sA1) = pal1;
        }
        *(uint4*)(sBh + bBuf + sB0) = pbh; *(uint4*)(sBl + bBuf + sB0) = pbl;
        __syncthreads();

        if (kt < 15) {
            int k0 = (kt + 1) * 32;
            if (A_FP32) {
                fa0 = *(const float4*)(Af + gA0 + k0); fa1 = *(const float4*)(Af + gA0 + k0 + 4);
                fb0 = *(const float4*)(Af + gA1 + k0); fb1 = *(const float4*)(Af + gA1 + k0 + 4);
            } else {
                pah0 = *(const uint4*)(Ah + gA0 + k0); pah1 = *(const uint4*)(Ah + gA1 + k0);
                pal0 = *(const uint4*)(Al + gA0 + k0); pal1 = *(const uint4*)(Al + gA1 + k0);
            }
            pbh = *(const uint4*)(Bh + gB0 + k0); pbl = *(const uint4*)(Bl + gB0 + k0);
        }

        const u32 aByte = (u32)(aBuf * 2), bByte = (u32)(bBuf * 2);
#pragma unroll
        for (int kk = 0; kk < 2; kk++) {
            const u32 kadd = kk * 32;
            u32 a_h[2][4], a_l[2][4];
            ldsm_x4(a_h[0][0], a_h[0][1], a_h[0][2], a_h[0][3], sbAh + aByte + aoffA0 + kadd);
            ldsm_x4(a_h[1][0], a_h[1][1], a_h[1][2], a_h[1][3], sbAh + aByte + aoffA1 + kadd);
            ldsm_x4(a_l[0][0], a_l[0][1], a_l[0][2], a_l[0][3], sbAl + aByte + aoffA0 + kadd);
            ldsm_x4(a_l[1][0], a_l[1][1], a_l[1][2], a_l[1][3], sbAl + aByte + aoffA1 + kadd);

            u32 t0, t1, t2, t3;
            u32 b_h[4][2], b_l[4][2];
            ldsm_x4(t0, t1, t2, t3, sbBh + bByte + aoffB0 + kadd);
            b_h[0][0] = t0; b_h[0][1] = t2; b_h[1][0] = t1; b_h[1][1] = t3;
            ldsm_x4(t0, t1, t2, t3, sbBh + bByte + aoffB1 + kadd);
            b_h[2][0] = t0; b_h[2][1] = t2; b_h[3][0] = t1; b_h[3][1] = t3;
            ldsm_x4(t0, t1, t2, t3, sbBl + bByte + aoffB0 + kadd);
            b_l[0][0] = t0; b_l[0][1] = t2; b_l[1][0] = t1; b_l[1][1] = t3;
            ldsm_x4(t0, t1, t2, t3, sbBl + bByte + aoffB1 + kadd);
            b_l[2][0] = t0; b_l[2][1] = t2; b_l[3][0] = t1; b_l[3][1] = t3;

#pragma unroll
            for (int s = 0; s < 3; s++) {
#pragma unroll
                for (int mi = 0; mi < 2; mi++)
#pragma unroll
                    for (int ni = 0; ni < 4; ni++) {
                        const u32* aa = (s == 2) ? a_l[mi] : a_h[mi];
                        const u32* bb = (s == 1) ? b_l[ni] : b_h[ni];
                        mma_bf16(acc[mi][ni], aa, bb);
                    }
            }
        }
    }

    const int grp = lane >> 2;
    const int qc  = (lane & 3) * 2;
#pragma unroll
    for (int mi = 0; mi < 2; mi++) {
        const int r0 = bm + wm * 32 + mi * 16 + grp;
        const int r1 = r0 + 8;
#pragma unroll
        for (int ni = 0; ni < 4; ni++) {
            const int col = bn + wn * 32 + ni * 8 + qc;
            float bv0 = __ldg(&bias[col]), bv1 = __ldg(&bias[col + 1]);
            float v00 = acc[mi][ni][0] + bv0, v01 = acc[mi][ni][1] + bv1;
            float v10 = acc[mi][ni][2] + bv0, v11 = acc[mi][ni][3] + bv1;
            if (GELU_SPLIT) {
                v00 = gelu_erf(v00); v01 = gelu_erf(v01);
                v10 = gelu_erf(v10); v11 = gelu_erf(v11);
                bf16 h0, h1, l0, l1;
                split_bf16(v00, h0, l0); split_bf16(v01, h1, l1);
                size_t i0 = (size_t)r0 * 256 + (col >> 1);
                reinterpret_cast<__nv_bfloat162*>(outHh)[i0] = __halves2bfloat162(h0, h1);
                reinterpret_cast<__nv_bfloat162*>(outHl)[i0] = __halves2bfloat162(l0, l1);
                split_bf16(v10, h0, l0); split_bf16(v11, h1, l1);
                size_t i1 = (size_t)r1 * 256 + (col >> 1);
                reinterpret_cast<__nv_bfloat162*>(outHh)[i1] = __halves2bfloat162(h0, h1);
                reinterpret_cast<__nv_bfloat162*>(outHl)[i1] = __halves2bfloat162(l0, l1);
            } else {
                if (col < Nvalid) {
                    *(float2*)(outF + (size_t)r0 * Nvalid + col) = make_float2(v00, v01);
                    *(float2*)(outF + (size_t)r1 * Nvalid + col) = make_float2(v10, v11);
                }
            }
        }
    }
}

// ================= overlap-add -> rec bf16 split [b][l][8] =================
__global__ void overlap_add_v3(const float* __restrict__ patches,
                               bf16* __restrict__ rech, bf16* __restrict__ recl)
{
    const int b  = blockIdx.y;
    const int l  = blockIdx.x * 256 + threadIdx.x;
    if (l >= L_) return;

    int i_lo = l - (T_ - 1);
    i_lo = (i_lo > 0) ? (i_lo + STRIDE_ - 1) / STRIDE_ : 0;
    int i_hi = l / STRIDE_;
    if (i_hi > P_ - 1) i_hi = P_ - 1;

    int np = 0, pi[2], pt[2];
    float wv[2], ws = 0.0f;
    for (int i = i_lo; i <= i_hi; i++) {
        int t = l - i * STRIDE_;
        float w;
        if (t < 50)        w = (float)t * (1.0f / 49.0f);
        else if (t >= 150) w = (float)(199 - t) * (1.0f / 49.0f);
        else               w = 1.0f;
        pi[np] = i; pt[np] = t; wv[np] = w; ws += w; np++;
    }
    float ews = fmaxf(ws, 1e-8f);

    unsigned short hh[8], ll[8];
#pragma unroll
    for (int c = 0; c < 8; c++) {
        float v = 0.0f;
        for (int j = 0; j < np; j++)
            v += patches[(((size_t)b * P_ + pi[j]) * C_ + c) * T_ + pt[j]] * wv[j];
        v = v / ews;
        bf16 h, lo; split_bf16(v, h, lo);
        hh[c] = __bfloat16_as_ushort(h);
        ll[c] = __bfloat16_as_ushort(lo);
    }
    size_t o = ((size_t)b * L_ + l) * 8;
    *(uint4*)(rech + o) = *(uint4*)hh;
    *(uint4*)(recl + o) = *(uint4*)ll;
}

// ================= conv1 v2: 256-pos tile, warp m32, B-ldsm shared =================
#define C1ROWS 271
#define C1SM (2 * (C1ROWS * 40 * 2) + 2 * (32 * 136 * 2))
__global__ void __launch_bounds__(256) conv1_hmma(
    const bf16* __restrict__ rech, const bf16* __restrict__ recl,
    const bf16* __restrict__ wh, const bf16* __restrict__ wl,
    const float* __restrict__ bias,
    bf16* __restrict__ r1h, bf16* __restrict__ r1l)
{
    extern __shared__ __align__(16) char dsm1[];
    bf16* sXh = (bf16*)dsm1;
    bf16* sXl = sXh + C1ROWS * 40;
    bf16* sWh = sXl + C1ROWS * 40;
    bf16* sWl = sWh + 32 * 136;

    const int tid  = threadIdx.x;
    const int lane = tid & 31;
    const int wm   = tid >> 5;
    const int b    = blockIdx.y;
    const int t0   = blockIdx.x * 256;

    for (int i = tid; i < 32 * 64; i += 256) {
        int r = i >> 6, q = i & 63;
        ((u32*)sWh)[r * 68 + q] = ((const u32*)wh)[r * 64 + q];
        ((u32*)sWl)[r * 68 + q] = ((const u32*)wl)[r * 64 + q];
    }
    for (int i = tid; i < C1ROWS * 2; i += 256) {
        int r = i >> 1, half = i & 1;
        int gp = t0 + r - 7 + half;
        uint4 vh = make_uint4(0,0,0,0), vl = vh;
        if (gp >= 0 && gp < L_) {
            size_t o = ((size_t)b * L_ + gp) * 8;
            vh = *(const uint4*)(rech + o);
            vl = *(const uint4*)(recl + o);
        }
        *(uint4*)(sXh + r * 40 + half * 8) = vh;
        *(uint4*)(sXl + r * 40 + half * 8) = vl;
    }
    __syncthreads();

    const u32 sbXh = smem_u32(sXh), sbXl = smem_u32(sXl);
    const u32 sbWh = smem_u32(sWh), sbWl = smem_u32(sWl);
    const int lrow = lane & 15;
    const int lhalf = (lane >> 4) * 8;
    const int grp = lane >> 2, qc = (lane & 3) * 2;

    float acc[2][4][4];
#pragma unroll
    for (int mi = 0; mi < 2; mi++)
#pragma unroll
        for (int ni = 0; ni < 4; ni++)
#pragma unroll
            for (int q = 0; q < 4; q++) acc[mi][ni][q] = 0.0f;

#pragma unroll
    for (int k = 0; k < 8; k++) {
        u32 ah[2][4], al[2][4];
#pragma unroll
        for (int mi = 0; mi < 2; mi++) {
            u32 aadd = (u32)((wm * 32 + mi * 16 + lrow + 2 * k) * 40 + lhalf) * 2;
            ldsm_x4(ah[mi][0], ah[mi][1], ah[mi][2], ah[mi][3], sbXh + aadd);
            ldsm_x4(al[mi][0], al[mi][1], al[mi][2], al[mi][3], sbXl + aadd);
        }
        u32 t0r, t1r, t2r, t3r;
        u32 bh[4][2], bl[4][2];
#pragma unroll
        for (int na2 = 0; na2 < 2; na2++) {
            u32 badd = (u32)((na2 * 16 + lrow) * 136 + k * 16 + lhalf) * 2;
            ldsm_x4(t0r, t1r, t2r, t3r, sbWh + badd);
            bh[na2*2][0] = t0r; bh[na2*2][1] = t2r;
            bh[na2*2+1][0] = t1r; bh[na2*2+1][1] = t3r;
            ldsm_x4(t0r, t1r, t2r, t3r, sbWl + badd);
            bl[na2*2][0] = t0r; bl[na2*2][1] = t2r;
            bl[na2*2+1][0] = t1r; bl[na2*2+1][1] = t3r;
        }
#pragma unroll
        for (int s = 0; s < 3; s++)
#pragma unroll
            for (int mi = 0; mi < 2; mi++)
#pragma unroll
                for (int ni = 0; ni < 4; ni++) {
                    const u32* aa = (s == 2) ? al[mi] : ah[mi];
                    const u32* bb = (s == 1) ? bl[ni] : bh[ni];
                    mma_bf16(acc[mi][ni], aa, bb);
                }
    }
    __syncthreads();

    u32* stgh = (u32*)sXh;   // 256*17 u32 = 17408B <= 21680B
    u32* stgl = (u32*)sXl;
#pragma unroll
    for (int mi = 0; mi < 2; mi++)
#pragma unroll
        for (int ni = 0; ni < 4; ni++) {
            int ch = ni * 8 + qc;
            float bv0 = __ldg(&bias[ch]), bv1 = __ldg(&bias[ch + 1]);
            int p0 = wm * 32 + mi * 16 + grp, p1 = p0 + 8;
            float v00 = gelu_erf(acc[mi][ni][0] + bv0), v01 = gelu_erf(acc[mi][ni][1] + bv1);
            float v10 = gelu_erf(acc[mi][ni][2] + bv0), v11 = gelu_erf(acc[mi][ni][3] + bv1);
            bf16 h0, h1, l0, l1;
            split_bf16(v00, h0, l0); split_bf16(v01, h1, l1);
            __nv_bfloat162 th = __halves2bfloat162(h0, h1), tl = __halves2bfloat162(l0, l1);
            stgh[p0 * 17 + ni * 4 + (lane & 3)] = *(u32*)&th;
            stgl[p0 * 17 + ni * 4 + (lane & 3)] = *(u32*)&tl;
            split_bf16(v10, h0, l0); split_bf16(v11, h1, l1);
            th = __halves2bfloat162(h0, h1); tl = __halves2bfloat162(l0, l1);
            stgh[p1 * 17 + ni * 4 + (lane & 3)] = *(u32*)&th;
            stgl[p1 * 17 + ni * 4 + (lane & 3)] = *(u32*)&tl;
        }
    __syncthreads();
    for (int i = tid; i < 256 * 16; i += 256) {
        int p = i >> 4, q = i & 15;
        int l = t0 + p;
        if (l < L_) {
            size_t o = ((size_t)b * L_ + l) * 16 + q;
            ((u32*)r1h)[o] = stgh[p * 17 + q];
            ((u32*)r1l)[o] = stgl[p * 17 + q];
        }
    }
}

// ================= conv2 v2: 256-pos tile, warp m32 =================
#define C2ROWS 272
#define C2SM (2 * (C2ROWS * 40 * 2) + 2 * (16 * 488 * 2))
__global__ void __launch_bounds__(256) conv2_hmma(
    const bf16* __restrict__ r1h, const bf16* __restrict__ r1l,
    const bf16* __restrict__ wh, const bf16* __restrict__ wl,
    const float* __restrict__ bias,
    bf16* __restrict__ r2h, bf16* __restrict__ r2l)
{
    extern __shared__ __align__(16) char dsm2[];
    bf16* sXh = (bf16*)dsm2;
    bf16* sXl = sXh + C2ROWS * 40;
    bf16* sWh = sXl + C2ROWS * 40;
    bf16* sWl = sWh + 16 * 488;

    const int tid  = threadIdx.x;
    const int lane = tid & 31;
    const int wm   = tid >> 5;
    const int b    = blockIdx.y;
    const int t0   = blockIdx.x * 256;

    for (int i = tid; i < 16 * 240; i += 256) {
        int r = i / 240, c = i - r * 240;
        ((u32*)sWh)[r * 244 + c] = ((const u32*)wh)[r * 240 + c];
        ((u32*)sWl)[r * 244 + c] = ((const u32*)wl)[r * 240 + c];
    }
    for (int i = tid; i < C2ROWS * 4; i += 256) {
        int r = i >> 2, q = i & 3;
        int gp = t0 + r - 7;
        uint4 vh = make_uint4(0,0,0,0), vl = vh;
        if (gp >= 0 && gp < L_) {
            size_t o = ((size_t)b * L_ + gp) * 32 + q * 8;
            vh = *(const uint4*)(r1h + o);
            vl = *(const uint4*)(r1l + o);
        }
        *(uint4*)(sXh + r * 40 + q * 8) = vh;
        *(uint4*)(sXl + r * 40 + q * 8) = vl;
    }
    __syncthreads();

    const u32 sbXh = smem_u32(sXh), sbXl = smem_u32(sXl);
    const u32 sbWh = smem_u32(sWh), sbWl = smem_u32(sWl);
    const int lrow = lane & 15;
    const int lhalf = (lane >> 4) * 8;
    const u32 boff  = sbWh + ((lane & 15) * 488 + lhalf) * 2;
    const u32 boffl = sbWl + ((lane & 15) * 488 + lhalf) * 2;
    const int grp = lane >> 2, qc = (lane & 3) * 2;

    float acc[2][2][4];
#pragma unroll
    for (int mi = 0; mi < 2; mi++)
#pragma unroll
        for (int ni = 0; ni < 2; ni++)
#pragma unroll
            for (int q = 0; q < 4; q++) acc[mi][ni][q] = 0.0f;

#pragma unroll 2
    for (int ks = 0; ks < 30; ks++) {
        const int k   = ks >> 1;
        const int icb = (ks & 1) * 16;
        u32 ah[2][4], al[2][4];
#pragma unroll
        for (int mi = 0; mi < 2; mi++) {
            u32 aadd = (u32)((wm * 32 + mi * 16 + lrow + k) * 40 + icb + lhalf) * 2;
            ldsm_x4(ah[mi][0], ah[mi][1], ah[mi][2], ah[mi][3], sbXh + aadd);
            ldsm_x4(al[mi][0], al[mi][1], al[mi][2], al[mi][3], sbXl + aadd);
        }
        u32 t0r, t1r, t2r, t3r;
        u32 bh[2][2], bl[2][2];
        ldsm_x4(t0r, t1r, t2r, t3r, boff + ks * 32);
        bh[0][0] = t0r; bh[0][1] = t2r; bh[1][0] = t1r; bh[1][1] = t3r;
        ldsm_x4(t0r, t1r, t2r, t3r, boffl + ks * 32);
        bl[0][0] = t0r; bl[0][1] = t2r; bl[1][0] = t1r; bl[1][1] = t3r;

#pragma unroll
        for (int s = 0; s < 3; s++)
#pragma unroll
            for (int mi = 0; mi < 2; mi++)
#pragma unroll
                for (int ni = 0; ni < 2; ni++) {
                    const u32* aa = (s == 2) ? al[mi] : ah[mi];
                    const u32* bb = (s == 1) ? bl[ni] : bh[ni];
                    mma_bf16(acc[mi][ni], aa, bb);
                }
    }
    __syncthreads();

    u32* stgh = (u32*)sXh;   // 256*9 u32 = 9216B
    u32* stgl = (u32*)sXl;
#pragma unroll
    for (int mi = 0; mi < 2; mi++)
#pragma unroll
        for (int ni = 0; ni < 2; ni++) {
            int ch = ni * 8 + qc;
            float bv0 = __ldg(&bias[ch]), bv1 = __ldg(&bias[ch + 1]);
            int p0 = wm * 32 + mi * 16 + grp, p1 = p0 + 8;
            float v00 = gelu_erf(acc[mi][ni][0] + bv0), v01 = gelu_erf(acc[mi][ni][1] + bv1);
            float v10 = gelu_erf(acc[mi][ni][2] + bv0), v11 = gelu_erf(acc[mi][ni][3] + bv1);
            bf16 h0, h1, l0, l1;
            split_bf16(v00, h0, l0); split_bf16(v01, h1, l1);
            __nv_bfloat162 th = __halves2bfloat162(h0, h1), tl = __halves2bfloat162(l0, l1);
            stgh[p0 * 9 + ni * 4 + (lane & 3)] = *(u32*)&th;
            stgl[p0 * 9 + ni * 4 + (lane & 3)] = *(u32*)&tl;
            split_bf16(v10, h0, l0); split_bf16(v11, h1, l1);
            th = __halves2bfloat162(h0, h1); tl = __halves2bfloat162(l0, l1);
            stgh[p1 * 9 + ni * 4 + (lane & 3)] = *(u32*)&th;
            stgl[p1 * 9 + ni * 4 + (lane & 3)] = *(u32*)&tl;
        }
    __syncthreads();
    for (int i = tid; i < 256 * 8; i += 256) {
        int p = i >> 3, q = i & 7;
        int l = t0 + p;
        if (l < L_) {
            size_t o = ((size_t)b * L_ + l) * 8 + q;
            ((u32*)r2h)[o] = stgh[p * 9 + q];
            ((u32*)r2l)[o] = stgl[p * 9 + q];
        }
    }
}

// ================= conv3 v2: 256-pos tile, warp m32, + residual + pointwise =================
#define C3ROWS 271
#define C3SM (2 * (C3ROWS * 40 * 2) + 2 * (8 * 248 * 2) + 256 * 9 * 4)
__global__ void __launch_bounds__(256) conv3_hmma(
    const bf16* __restrict__ r2h, const bf16* __restrict__ r2l,
    const bf16* __restrict__ wh, const bf16* __restrict__ wl,
    const float* __restrict__ bias,
    const bf16* __restrict__ rech, const bf16* __restrict__ recl,
    const float* __restrict__ pw, const float* __restrict__ pb,
    float* __restrict__ out)
{
    extern __shared__ __align__(16) char dsm3[];
    bf16* sXh = (bf16*)dsm3;
    bf16* sXl = sXh + C3ROWS * 40;
    bf16* sWh = sXl + C3ROWS * 40;
    bf16* sWl = sWh + 8 * 248;
    float* sF = (float*)(sWl + 8 * 248);

    const int tid  = threadIdx.x;
    const int lane = tid & 31;
    const int wm   = tid >> 5;
    const int b    = blockIdx.y;
    const int t0   = blockIdx.x * 256;

    for (int i = tid; i < 8 * 120; i += 256) {
        int r = i / 120, c = i - r * 120;
        ((u32*)sWh)[r * 124 + c] = ((const u32*)wh)[r * 120 + c];
        ((u32*)sWl)[r * 124 + c] = ((const u32*)wl)[r * 120 + c];
    }
    for (int i = tid; i < C3ROWS * 2; i += 256) {
        int r = i >> 1, q = i & 1;
        int gp = t0 + r - 7;
        uint4 vh = make_uint4(0,0,0,0), vl = vh;
        if (gp >= 0 && gp < L_) {
            size_t o = ((size_t)b * L_ + gp) * 16 + q * 8;
            vh = *(const uint4*)(r2h + o);
            vl = *(const uint4*)(r2l + o);
        }
        *(uint4*)(sXh + r * 40 + q * 8) = vh;
        *(uint4*)(sXl + r * 40 + q * 8) = vl;
    }
    __syncthreads();

    const u32 sbXh = smem_u32(sXh), sbXl = smem_u32(sXl);
    const u32 sbWh = smem_u32(sWh), sbWl = smem_u32(sWl);
    const int lrow = lane & 15;
    const int lhalf = (lane >> 4) * 8;
    const u32 bbase = ((lane & 7) * 248 + ((lane >> 3) & 1) * 8) * 2;
    const int grp = lane >> 2, qc = (lane & 3) * 2;

    float acc[2][4];
#pragma unroll
    for (int mi = 0; mi < 2; mi++)
#pragma unroll
        for (int q = 0; q < 4; q++) acc[mi][q] = 0.0f;

#pragma unroll
    for (int k = 0; k < 15; k++) {
        u32 ah[2][4], al[2][4];
#pragma unroll
        for (int mi = 0; mi < 2; mi++) {
            u32 aadd = (u32)((wm * 32 + mi * 16 + lrow + k) * 40 + lhalf) * 2;
            ldsm_x4(ah[mi][0], ah[mi][1], ah[mi][2], ah[mi][3], sbXh + aadd);
            ldsm_x4(al[mi][0], al[mi][1], al[mi][2], al[mi][3], sbXl + aadd);
        }
        u32 bh[2], bl[2];
        ldsm_x2(bh[0], bh[1], sbWh + bbase + k * 32);
        ldsm_x2(bl[0], bl[1], sbWl + bbase + k * 32);
#pragma unroll
        for (int mi = 0; mi < 2; mi++) mma_bf16(acc[mi], ah[mi], bh);
#pragma unroll
        for (int mi = 0; mi < 2; mi++) mma_bf16(acc[mi], ah[mi], bl);
#pragma unroll
        for (int mi = 0; mi < 2; mi++) mma_bf16(acc[mi], al[mi], bh);
    }
    __syncthreads();

    {
        float bv0 = __ldg(&bias[qc]), bv1 = __ldg(&bias[qc + 1]);
#pragma unroll
        for (int mi = 0; mi < 2; mi++) {
            int p0 = wm * 32 + mi * 16 + grp, p1 = p0 + 8;
            sF[p0 * 9 + qc]     = acc[mi][0] + bv0;
            sF[p0 * 9 + qc + 1] = acc[mi][1] + bv1;
            sF[p1 * 9 + qc]     = acc[mi][2] + bv0;
            sF[p1 * 9 + qc + 1] = acc[mi][3] + bv1;
        }
    }
    __syncthreads();

    {
        int l = t0 + tid;
        if (l < L_) {
            size_t ro = ((size_t)b * L_ + l) * 8;
            uint4 vh = *(const uint4*)(rech + ro);
            uint4 vl = *(const uint4*)(recl + ro);
            const unsigned short* hs = (const unsigned short*)&vh;
            const unsigned short* ls = (const unsigned short*)&vl;
            float resid[8];
#pragma unroll
            for (int c = 0; c < 8; c++) {
                float rv = __bfloat162float(__ushort_as_bfloat16(hs[c]))
                         + __bfloat162float(__ushort_as_bfloat16(ls[c]));
                resid[c] = rv + sF[tid * 9 + c];
            }
#pragma unroll
            for (int o = 0; o < 8; o++) {
                float v = __ldg(&pb[o]);
#pragma unroll
                for (int c = 0; c < 8; c++)
                    v += __ldg(&pw[o * C_ + c]) * resid[c];
                out[((size_t)b * C_ + o) * L_ + l] = v;
            }
        }
    }
}

// ---------------- launcher ----------------
extern "C" void kernel_launch(void* const* d_in, const int* in_sizes, int n_in,
                              void* d_out, int out_size)
{
    const float* X   = (const float*)d_in[0];
    const float* W1  = (const float*)d_in[1];
    const float* b1  = (const float*)d_in[2];
    const float* W2  = (const float*)d_in[3];
    const float* b2  = (const float*)d_in[4];
    const float* rw1 = (const float*)d_in[5];
    const float* rb1 = (const float*)d_in[6];
    const float* rw2 = (const float*)d_in[7];
    const float* rb2 = (const float*)d_in[8];
    const float* rw3 = (const float*)d_in[9];
    const float* rb3 = (const float*)d_in[10];
    const float* pw  = (const float*)d_in[11];
    const float* pb  = (const float*)d_in[12];
    float* out = (float*)d_out;

    bf16 *pHh, *pHl, *pW1th, *pW1tl, *pW2th, *pW2tl;
    bf16 *pRech, *pRecl, *pR1h, *pR1l, *pR2h, *pR2l;
    bf16 *pCw1h, *pCw1l, *pW2h, *pW2l, *pCw3h, *pCw3l;
    float *pPatches;
    cudaGetSymbolAddress((void**)&pHh,   g_Hh);
    cudaGetSymbolAddress((void**)&pHl,   g_Hl);
    cudaGetSymbolAddress((void**)&pW1th, g_W1th);
    cudaGetSymbolAddress((void**)&pW1tl, g_W1tl);
    cudaGetSymbolAddress((void**)&pW2th, g_W2th);
    cudaGetSymbolAddress((void**)&pW2tl, g_W2tl);
    cudaGetSymbolAddress((void**)&pPatches, g_patches);
    cudaGetSymbolAddress((void**)&pRech, g_rech);
    cudaGetSymbolAddress((void**)&pRecl, g_recl);
    cudaGetSymbolAddress((void**)&pR1h,  g_r1h);
    cudaGetSymbolAddress((void**)&pR1l,  g_r1l);
    cudaGetSymbolAddress((void**)&pR2h,  g_r2h);
    cudaGetSymbolAddress((void**)&pR2l,  g_r2l);
    cudaGetSymbolAddress((void**)&pCw1h, g_cw1h);
    cudaGetSymbolAddress((void**)&pCw1l, g_cw1l);
    cudaGetSymbolAddress((void**)&pW2h,  g_w2h);
    cudaGetSymbolAddress((void**)&pW2l,  g_w2l);
    cudaGetSymbolAddress((void**)&pCw3h, g_cw3h);
    cudaGetSymbolAddress((void**)&pCw3l, g_cw3l);

    cudaFuncSetAttribute(gemm_hmma<true,  true>,
                         cudaFuncAttributeMaxDynamicSharedMemorySize, GEMM_SMEM);
    cudaFuncSetAttribute(gemm_hmma<false, false>,
                         cudaFuncAttributeMaxDynamicSharedMemorySize, GEMM_SMEM);
    cudaFuncSetAttribute(conv1_hmma, cudaFuncAttributeMaxDynamicSharedMemorySize, C1SM);
    cudaFuncSetAttribute(conv2_hmma, cudaFuncAttributeMaxDynamicSharedMemorySize, C2SM);
    cudaFuncSetAttribute(conv3_hmma, cudaFuncAttributeMaxDynamicSharedMemorySize, C3SM);

    const int convGrid = (L_ + 255) / 256;   // 8

    // order: GEMM2 lands in ncu capture slot (#4)
    transp_split_kernel<<<(512*512 + 255) / 256, 256>>>(W1, pW1th, pW1tl, 512, 512, 512); // 1
    gemm_hmma<true, true><<<dim3(8, M_ / 128), 256, GEMM_SMEM>>>(                         // 2
        X, nullptr, nullptr, pW1th, pW1tl, b1, 512, pHh, pHl, nullptr);
    transp_split_kernel<<<(256*512 + 255) / 256, 256>>>(W2, pW2th, pW2tl, 512, 200, 256); // 3
    gemm_hmma<false, false><<<dim3(4, M_ / 128), 256, GEMM_SMEM>>>(                       // 4 <- ncu
        nullptr, pHh, pHl, pW2th, pW2tl, b2, 200, nullptr, nullptr, pPatches);
    overlap_add_v3<<<dim3((L_ + 255) / 256, B_), 256>>>(pPatches, pRech, pRecl);          // 5
    w1c_prep_kernel<<<(32*128 + 255) / 256, 256>>>(rw1, pCw1h, pCw1l);                    // 6
    conv1_hmma<<<dim3(convGrid, B_), 256, C1SM>>>(pRech, pRecl, pCw1h, pCw1l, rb1,        // 7
                                                  pR1h, pR1l);
    w2_prep_kernel<<<(16*480 + 255) / 256, 256>>>(rw2, pW2h, pW2l);                       // 8
    conv2_hmma<<<dim3(convGrid, B_), 256, C2SM>>>(pR1h, pR1l, pW2h, pW2l, rb2,            // 9
                                                  pR2h, pR2l);
    w3c_prep_kernel<<<(8*240 + 255) / 256, 256>>>(rw3, pCw3h, pCw3l);                     // 10
    conv3_hmma<<<dim3(convGrid, B_), 256, C3SM>>>(pR2h, pR2l, pCw3h, pCw3l, rb3,          // 11
                                                  pRech, pRecl, pw, pb, out);
}